// round 5
// baseline (speedup 1.0000x reference)
#include <cuda_runtime.h>
#include <math.h>

#define BATCH   2
#define SEQ     2048
#define DMODEL  1024
#define NHEADS  16
#define DK      64
#define MROWS   (BATCH * SEQ)   // 4096

// -------------------- scratch (__device__ globals; no allocations) ---------
__device__ float g_q[(size_t)BATCH * NHEADS * SEQ * DK];  // [b,h,s,dk]
__device__ float g_k[(size_t)BATCH * NHEADS * SEQ * DK];
__device__ float g_v[(size_t)BATCH * NHEADS * SEQ * DK];
__device__ float g_o[(size_t)MROWS * DMODEL];             // [b,s,h,dk] = [m, d]

// ===========================================================================
// QKV projection: C = X · Wᵀ, epilogue remaps [m,e] -> [b,h,s,dk].
// Tile 128x128x8, 256 threads, 8x8 microtile.
// ===========================================================================
__global__ __launch_bounds__(256) void qkv_gemm_kernel(
    const float* __restrict__ X,
    const float* __restrict__ Wq,
    const float* __restrict__ Wk,
    const float* __restrict__ Wv)
{
    const float* B   = (blockIdx.z == 0) ? Wq : (blockIdx.z == 1 ? Wk : Wv);
    float*       Cbf = (blockIdx.z == 0) ? g_q : (blockIdx.z == 1 ? g_k : g_v);

    __shared__ float As[8][132];
    __shared__ float Bs[8][132];

    const int tid = threadIdx.x;
    const int ty  = tid >> 4;        // 0..15 (rows)
    const int tx  = tid & 15;        // 0..15 (cols)
    const int m0  = blockIdx.y * 128;
    const int n0  = blockIdx.x * 128;

    const int lrow = tid >> 1;             // 0..127
    const int lk4  = (tid & 1) << 2;       // 0 or 4

    float acc[8][8];
#pragma unroll
    for (int i = 0; i < 8; i++)
#pragma unroll
        for (int j = 0; j < 8; j++) acc[i][j] = 0.0f;

    const float* Arow = X + (size_t)(m0 + lrow) * DMODEL + lk4;
    const float* Brow = B + (size_t)(n0 + lrow) * DMODEL + lk4;

    for (int k0 = 0; k0 < DMODEL; k0 += 8) {
        float4 av = *(const float4*)(Arow + k0);
        float4 bv = *(const float4*)(Brow + k0);
        __syncthreads();
        As[lk4 + 0][lrow] = av.x; As[lk4 + 1][lrow] = av.y;
        As[lk4 + 2][lrow] = av.z; As[lk4 + 3][lrow] = av.w;
        Bs[lk4 + 0][lrow] = bv.x; Bs[lk4 + 1][lrow] = bv.y;
        Bs[lk4 + 2][lrow] = bv.z; Bs[lk4 + 3][lrow] = bv.w;
        __syncthreads();
#pragma unroll
        for (int k = 0; k < 8; k++) {
            float4 a0 = *(const float4*)&As[k][ty * 8];
            float4 a1 = *(const float4*)&As[k][ty * 8 + 4];
            float4 b0 = *(const float4*)&Bs[k][tx * 8];
            float4 b1 = *(const float4*)&Bs[k][tx * 8 + 4];
            float ar[8] = {a0.x, a0.y, a0.z, a0.w, a1.x, a1.y, a1.z, a1.w};
            float br[8] = {b0.x, b0.y, b0.z, b0.w, b1.x, b1.y, b1.z, b1.w};
#pragma unroll
            for (int i = 0; i < 8; i++)
#pragma unroll
                for (int j = 0; j < 8; j++)
                    acc[i][j] += ar[i] * br[j];
        }
    }

    // epilogue: remap to [b, h, s, dk]
#pragma unroll
    for (int i = 0; i < 8; i++) {
        const int m = m0 + ty * 8 + i;
        const int b = m >> 11;          // / SEQ
        const int s = m & (SEQ - 1);
#pragma unroll
        for (int j = 0; j < 8; j++) {
            const int e  = n0 + tx * 8 + j;
            const int h  = e >> 6;
            const int dk = e & 63;
            Cbf[(((size_t)b * NHEADS + h) * SEQ + s) * DK + dk] = acc[i][j];
        }
    }
}

// ===========================================================================
// Causal flash attention (fp32). One block per (b*h, qtile of 64 rows).
// BM=64, BN=32, 256 threads: thread (ty,tx) owns 4 rows x {2 score cols / 4 O cols}.
// ===========================================================================
__global__ __launch_bounds__(256) void attn_kernel()
{
    __shared__ float Qt[64][68];   // Q transposed: Qt[d][row]
    __shared__ float Kt[64][34];   // K transposed: Kt[d][key]
    __shared__ float Vs[32][68];   // V: Vs[key][d]
    __shared__ float Pt[32][65];   // P transposed: Pt[key][row]

    const int tid = threadIdx.x;
    const int ty  = tid >> 4;      // 0..15 -> rows ty*4..ty*4+3
    const int tx  = tid & 15;      // 0..15
    const int bh  = blockIdx.y;    // 0..31
    const int b   = bh >> 4;
    const int h   = bh & 15;
    const int qt  = (int)gridDim.x - 1 - (int)blockIdx.x;  // heavy blocks first
    const int q0  = qt * 64;

    const float* Qb = g_q + (size_t)bh * SEQ * DK;
    const float* Kb = g_k + (size_t)bh * SEQ * DK;
    const float* Vb = g_v + (size_t)bh * SEQ * DK;

    // load Q tile (transposed)
#pragma unroll
    for (int r = 0; r < 16; r++) {
        const int idx = r * 256 + tid;
        const int i = idx >> 6, d = idx & 63;
        Qt[d][i] = Qb[(size_t)(q0 + i) * DK + d];
    }

    float m_i[4], l_i[4], acc[4][4];
#pragma unroll
    for (int i = 0; i < 4; i++) {
        m_i[i] = -1e30f;
        l_i[i] = 0.0f;
#pragma unroll
        for (int j = 0; j < 4; j++) acc[i][j] = 0.0f;
    }

    const int ntiles = (qt + 1) * 2;   // keys [0, q0+64) in BN=32 steps
    for (int kt = 0; kt < ntiles; kt++) {
        const int k0 = kt * 32;
        __syncthreads();   // prior iteration's reads of Kt/Vs/Pt complete
#pragma unroll
        for (int r = 0; r < 8; r++) {
            const int idx = r * 256 + tid;
            const int j = idx >> 6, d = idx & 63;
            Kt[d][j] = Kb[(size_t)(k0 + j) * DK + d];
            Vs[j][d] = Vb[(size_t)(k0 + j) * DK + d];
        }
        __syncthreads();

        // S = Q · Kᵀ  (4 rows x 2 cols per thread)
        float s0[4] = {0.f, 0.f, 0.f, 0.f};
        float s1[4] = {0.f, 0.f, 0.f, 0.f};
#pragma unroll 16
        for (int d = 0; d < 64; d++) {
            float4 q4 = *(const float4*)&Qt[d][ty * 4];
            float2 k2 = *(const float2*)&Kt[d][tx * 2];
            s0[0] += q4.x * k2.x;  s1[0] += q4.x * k2.y;
            s0[1] += q4.y * k2.x;  s1[1] += q4.y * k2.y;
            s0[2] += q4.z * k2.x;  s1[2] += q4.z * k2.y;
            s0[3] += q4.w * k2.x;  s1[3] += q4.w * k2.y;
        }

        const float sc = 0.125f;               // 1/sqrt(64)
        const bool need_mask = (k0 + 31 > q0);
        const int kc0 = k0 + tx * 2;
        const int kc1 = kc0 + 1;
#pragma unroll
        for (int i = 0; i < 4; i++) {
            float a = s0[i] * sc;
            float c = s1[i] * sc;
            if (need_mask) {
                const int qi = q0 + ty * 4 + i;
                if (kc0 > qi) a = -1e30f;
                if (kc1 > qi) c = -1e30f;
            }
            s0[i] = a; s1[i] = c;
        }

        // online softmax per row (16-lane reductions; lanes of a row are contiguous)
#pragma unroll
        for (int i = 0; i < 4; i++) {
            float mx = fmaxf(s0[i], s1[i]);
            mx = fmaxf(mx, __shfl_xor_sync(0xffffffffu, mx, 1));
            mx = fmaxf(mx, __shfl_xor_sync(0xffffffffu, mx, 2));
            mx = fmaxf(mx, __shfl_xor_sync(0xffffffffu, mx, 4));
            mx = fmaxf(mx, __shfl_xor_sync(0xffffffffu, mx, 8));
            const float m_new = fmaxf(m_i[i], mx);
            const float alpha = __expf(m_i[i] - m_new);
            m_i[i] = m_new;
            const float p0 = __expf(s0[i] - m_new);
            const float p1 = __expf(s1[i] - m_new);
            float rs = p0 + p1;
            rs += __shfl_xor_sync(0xffffffffu, rs, 1);
            rs += __shfl_xor_sync(0xffffffffu, rs, 2);
            rs += __shfl_xor_sync(0xffffffffu, rs, 4);
            rs += __shfl_xor_sync(0xffffffffu, rs, 8);
            l_i[i] = l_i[i] * alpha + rs;
#pragma unroll
            for (int j = 0; j < 4; j++) acc[i][j] *= alpha;
            Pt[tx * 2 + 0][ty * 4 + i] = p0;
            Pt[tx * 2 + 1][ty * 4 + i] = p1;
        }
        __syncthreads();

        // O += P · V  (4 rows x 4 dk cols per thread)
#pragma unroll 8
        for (int j = 0; j < 32; j++) {
            float4 v4 = *(const float4*)&Vs[j][tx * 4];
            const float pr0 = Pt[j][ty * 4 + 0];
            const float pr1 = Pt[j][ty * 4 + 1];
            const float pr2 = Pt[j][ty * 4 + 2];
            const float pr3 = Pt[j][ty * 4 + 3];
            acc[0][0] += pr0 * v4.x; acc[0][1] += pr0 * v4.y; acc[0][2] += pr0 * v4.z; acc[0][3] += pr0 * v4.w;
            acc[1][0] += pr1 * v4.x; acc[1][1] += pr1 * v4.y; acc[1][2] += pr1 * v4.z; acc[1][3] += pr1 * v4.w;
            acc[2][0] += pr2 * v4.x; acc[2][1] += pr2 * v4.y; acc[2][2] += pr2 * v4.z; acc[2][3] += pr2 * v4.w;
            acc[3][0] += pr3 * v4.x; acc[3][1] += pr3 * v4.y; acc[3][2] += pr3 * v4.z; acc[3][3] += pr3 * v4.w;
        }
    }

    // write O in [b, s, h, dk] layout (== concat [m, d])
#pragma unroll
    for (int i = 0; i < 4; i++) {
        const float inv = 1.0f / l_i[i];
        const int s = q0 + ty * 4 + i;
        const size_t base = (((size_t)b * SEQ + s) * NHEADS + h) * DK + tx * 4;
        g_o[base + 0] = acc[i][0] * inv;
        g_o[base + 1] = acc[i][1] * inv;
        g_o[base + 2] = acc[i][2] * inv;
        g_o[base + 3] = acc[i][3] * inv;
    }
}

// ===========================================================================
// Output projection: out = g_o · Woᵀ + bo
// ===========================================================================
__global__ __launch_bounds__(256) void out_gemm_kernel(
    const float* __restrict__ W,
    const float* __restrict__ bias,
    float* __restrict__ C)
{
    __shared__ float As[8][132];
    __shared__ float Bs[8][132];

    const int tid = threadIdx.x;
    const int ty  = tid >> 4;
    const int tx  = tid & 15;
    const int m0  = blockIdx.y * 128;
    const int n0  = blockIdx.x * 128;

    const int lrow = tid >> 1;
    const int lk4  = (tid & 1) << 2;

    float acc[8][8];
#pragma unroll
    for (int i = 0; i < 8; i++)
#pragma unroll
        for (int j = 0; j < 8; j++) acc[i][j] = 0.0f;

    const float* Arow = g_o + (size_t)(m0 + lrow) * DMODEL + lk4;
    const float* Brow = W   + (size_t)(n0 + lrow) * DMODEL + lk4;

    for (int k0 = 0; k0 < DMODEL; k0 += 8) {
        float4 av = *(const float4*)(Arow + k0);
        float4 bv = *(const float4*)(Brow + k0);
        __syncthreads();
        As[lk4 + 0][lrow] = av.x; As[lk4 + 1][lrow] = av.y;
        As[lk4 + 2][lrow] = av.z; As[lk4 + 3][lrow] = av.w;
        Bs[lk4 + 0][lrow] = bv.x; Bs[lk4 + 1][lrow] = bv.y;
        Bs[lk4 + 2][lrow] = bv.z; Bs[lk4 + 3][lrow] = bv.w;
        __syncthreads();
#pragma unroll
        for (int k = 0; k < 8; k++) {
            float4 a0 = *(const float4*)&As[k][ty * 8];
            float4 a1 = *(const float4*)&As[k][ty * 8 + 4];
            float4 b0 = *(const float4*)&Bs[k][tx * 8];
            float4 b1 = *(const float4*)&Bs[k][tx * 8 + 4];
            float ar[8] = {a0.x, a0.y, a0.z, a0.w, a1.x, a1.y, a1.z, a1.w};
            float br[8] = {b0.x, b0.y, b0.z, b0.w, b1.x, b1.y, b1.z, b1.w};
#pragma unroll
            for (int i = 0; i < 8; i++)
#pragma unroll
                for (int j = 0; j < 8; j++)
                    acc[i][j] += ar[i] * br[j];
        }
    }

#pragma unroll
    for (int i = 0; i < 8; i++) {
        const int m = m0 + ty * 8 + i;
#pragma unroll
        for (int j = 0; j < 8; j++) {
            const int e = n0 + tx * 8 + j;
            C[(size_t)m * DMODEL + e] = acc[i][j] + bias[e];
        }
    }
}

// ===========================================================================
extern "C" void kernel_launch(void* const* d_in, const int* in_sizes, int n_in,
                              void* d_out, int out_size)
{
    (void)in_sizes; (void)n_in; (void)out_size;
    const float* x  = (const float*)d_in[0];
    const float* Wq = (const float*)d_in[1];
    const float* Wk = (const float*)d_in[2];
    const float* Wv = (const float*)d_in[3];
    const float* Wo = (const float*)d_in[4];
    const float* bo = (const float*)d_in[5];
    // d_in[6] = mask, unused (causality computed analytically)
    float* out = (float*)d_out;

    qkv_gemm_kernel<<<dim3(DMODEL / 128, MROWS / 128, 3), 256>>>(x, Wq, Wk, Wv);
    attn_kernel<<<dim3(SEQ / 64, BATCH * NHEADS), 256>>>();
    out_gemm_kernel<<<dim3(DMODEL / 128, MROWS / 128), 256>>>(Wo, bo, out);
}

// round 8
// speedup vs baseline: 1.4351x; 1.4351x over previous
#include <cuda_runtime.h>
#include <cuda_bf16.h>
#include <math.h>
#include <stdint.h>

#define BATCH   2
#define SEQ     2048
#define DMODEL  1024
#define NHEADS  16
#define DK      64
#define MROWS   (BATCH * SEQ)   // 4096

// -------------------- scratch (__device__ globals; no allocations) ---------
__device__ float g_q[(size_t)BATCH * NHEADS * SEQ * DK];  // [b,h,s,dk]
__device__ float g_k[(size_t)BATCH * NHEADS * SEQ * DK];
__device__ float g_v[(size_t)BATCH * NHEADS * SEQ * DK];
__device__ float g_o[(size_t)MROWS * DMODEL];             // [b,s,h,dk] = [m, d]

// split-bf16 operands
__device__ __nv_bfloat16 g_Xh[(size_t)MROWS * DMODEL];
__device__ __nv_bfloat16 g_Xl[(size_t)MROWS * DMODEL];
__device__ __nv_bfloat16 g_Wh[4][(size_t)DMODEL * DMODEL];  // q,k,v,o
__device__ __nv_bfloat16 g_Wl[4][(size_t)DMODEL * DMODEL];
__device__ __nv_bfloat16 g_Oh[(size_t)MROWS * DMODEL];
__device__ __nv_bfloat16 g_Ol[(size_t)MROWS * DMODEL];

// ===========================================================================
// warp-MMA helpers (arch-portable sm_80+ ISA; tcgen05 is rejected by this
// harness's compute_103 virtual-arch build)
// ===========================================================================
__device__ __forceinline__ uint32_t smem_u32(const void* p) {
    uint32_t a;
    asm("{ .reg .u64 t; cvta.to.shared.u64 t, %1; cvt.u32.u64 %0, t; }"
        : "=r"(a) : "l"(p));
    return a;
}

__device__ __forceinline__ void ldsm_x4(uint32_t& r0, uint32_t& r1,
                                        uint32_t& r2, uint32_t& r3, uint32_t addr) {
    asm volatile("ldmatrix.sync.aligned.m8n8.x4.shared.b16 {%0,%1,%2,%3}, [%4];"
                 : "=r"(r0), "=r"(r1), "=r"(r2), "=r"(r3) : "r"(addr));
}

__device__ __forceinline__ void mma16816(float* d, const uint32_t* a, const uint32_t* b) {
    asm volatile(
        "mma.sync.aligned.m16n8k16.row.col.f32.bf16.bf16.f32 "
        "{%0,%1,%2,%3}, {%4,%5,%6,%7}, {%8,%9}, {%0,%1,%2,%3};"
        : "+f"(d[0]), "+f"(d[1]), "+f"(d[2]), "+f"(d[3])
        : "r"(a[0]), "r"(a[1]), "r"(a[2]), "r"(a[3]), "r"(b[0]), "r"(b[1]));
}

// ===========================================================================
// fp32 -> (hi, lo) bf16 split.  which: 0=X, 1..4=Wq/Wk/Wv/Wo, 5=g_o
// ===========================================================================
__global__ void cvt_split_kernel(const float* __restrict__ src, int which, int n4)
{
    int i = blockIdx.x * blockDim.x + threadIdx.x;
    if (i >= n4) return;
    __nv_bfloat16 *hi, *lo;
    switch (which) {
        case 0: hi = g_Xh;    lo = g_Xl;    break;
        case 1: hi = g_Wh[0]; lo = g_Wl[0]; break;
        case 2: hi = g_Wh[1]; lo = g_Wl[1]; break;
        case 3: hi = g_Wh[2]; lo = g_Wl[2]; break;
        case 4: hi = g_Wh[3]; lo = g_Wl[3]; break;
        default: hi = g_Oh;   lo = g_Ol;    src = g_o; break;
    }
    float4 v = ((const float4*)src)[i];
    __nv_bfloat162 h0, h1, l0, l1;
    h0.x = __float2bfloat16(v.x); h0.y = __float2bfloat16(v.y);
    h1.x = __float2bfloat16(v.z); h1.y = __float2bfloat16(v.w);
    l0.x = __float2bfloat16(v.x - __bfloat162float(h0.x));
    l0.y = __float2bfloat16(v.y - __bfloat162float(h0.y));
    l1.x = __float2bfloat16(v.z - __bfloat162float(h1.x));
    l1.y = __float2bfloat16(v.w - __bfloat162float(h1.y));
    ((__nv_bfloat162*)hi)[2 * i + 0] = h0;
    ((__nv_bfloat162*)hi)[2 * i + 1] = h1;
    ((__nv_bfloat162*)lo)[2 * i + 0] = l0;
    ((__nv_bfloat162*)lo)[2 * i + 1] = l1;
}

// ===========================================================================
// Split-bf16 GEMM core: C[128,128] = A[128,K] · B[128,K]^T (three-pass
// hh + hl + lh), warp-level m16n8k16 MMA. 256 threads, warp grid 4(m) x 2(n).
// smem row stride 40 bf16 (80B): ldmatrix rows hit 8 distinct 16B phases.
// ===========================================================================
#define SA 40   // smem row stride in bf16 elems

__device__ __forceinline__ void gemm_tile_core(
    const __nv_bfloat16* __restrict__ Ah, const __nv_bfloat16* __restrict__ Al,
    const __nv_bfloat16* __restrict__ Bh, const __nv_bfloat16* __restrict__ Bl,
    int m0, int n0, float d[2][8][4])
{
    __shared__ __nv_bfloat16 sAh[128 * SA], sAl[128 * SA];
    __shared__ __nv_bfloat16 sBh[128 * SA], sBl[128 * SA];

    const int tid  = threadIdx.x;
    const int lane = tid & 31;
    const int wid  = tid >> 5;
    const int wm   = wid >> 1;       // 0..3 : rows wm*32
    const int wn   = wid & 1;        // 0..1 : cols wn*64

    const uint32_t aAh = smem_u32(sAh), aAl = smem_u32(sAl);
    const uint32_t aBh = smem_u32(sBh), aBl = smem_u32(sBl);

    // ldmatrix per-lane address pieces
    const int sub  = lane >> 3, l7 = lane & 7;
    const int arow = wm * 32 + l7 + (sub & 1) * 8;   // + mt*16
    const int akof = (sub >> 1) * 8;                 // + ks
    const int brow = wn * 64 + l7 + (sub >> 1) * 8;  // + g*16
    const int bkof = (sub & 1) * 8;                  // + ks

    // gmem staging: 2 parts x 4 matrices, uint4 (8 bf16) each
    const int grow = tid >> 2;          // + p*64
    const int gq   = (tid & 3) * 8;

#pragma unroll
    for (int mt = 0; mt < 2; mt++)
#pragma unroll
        for (int nt = 0; nt < 8; nt++)
#pragma unroll
            for (int c = 0; c < 4; c++) d[mt][nt][c] = 0.0f;

    uint4 va[2][4];
#pragma unroll
    for (int p = 0; p < 2; p++) {
        const size_t ga = (size_t)(m0 + p * 64 + grow) * DMODEL + gq;
        const size_t gb = (size_t)(n0 + p * 64 + grow) * DMODEL + gq;
        va[p][0] = *(const uint4*)(Ah + ga);
        va[p][1] = *(const uint4*)(Al + ga);
        va[p][2] = *(const uint4*)(Bh + gb);
        va[p][3] = *(const uint4*)(Bl + gb);
    }

    for (int it = 0; it < DMODEL / 32; it++) {
        __syncthreads();
#pragma unroll
        for (int p = 0; p < 2; p++) {
            const int so = (p * 64 + grow) * SA + gq;
            *(uint4*)(sAh + so) = va[p][0];
            *(uint4*)(sAl + so) = va[p][1];
            *(uint4*)(sBh + so) = va[p][2];
            *(uint4*)(sBl + so) = va[p][3];
        }
        if (it + 1 < DMODEL / 32) {
            const int k0 = (it + 1) * 32;
#pragma unroll
            for (int p = 0; p < 2; p++) {
                const size_t ga = (size_t)(m0 + p * 64 + grow) * DMODEL + k0 + gq;
                const size_t gb = (size_t)(n0 + p * 64 + grow) * DMODEL + k0 + gq;
                va[p][0] = *(const uint4*)(Ah + ga);
                va[p][1] = *(const uint4*)(Al + ga);
                va[p][2] = *(const uint4*)(Bh + gb);
                va[p][3] = *(const uint4*)(Bl + gb);
            }
        }
        __syncthreads();

#pragma unroll
        for (int s = 0; s < 2; s++) {
            const int ks = s * 16;
            uint32_t fAh[2][4], fAl[2][4], fBh[8][2], fBl[8][2];
#pragma unroll
            for (int mt = 0; mt < 2; mt++) {
                const uint32_t off = ((arow + mt * 16) * SA + ks + akof) * 2;
                ldsm_x4(fAh[mt][0], fAh[mt][1], fAh[mt][2], fAh[mt][3], aAh + off);
                ldsm_x4(fAl[mt][0], fAl[mt][1], fAl[mt][2], fAl[mt][3], aAl + off);
            }
#pragma unroll
            for (int g = 0; g < 4; g++) {
                const uint32_t off = ((brow + g * 16) * SA + ks + bkof) * 2;
                ldsm_x4(fBh[2 * g][0], fBh[2 * g][1], fBh[2 * g + 1][0], fBh[2 * g + 1][1], aBh + off);
                ldsm_x4(fBl[2 * g][0], fBl[2 * g][1], fBl[2 * g + 1][0], fBl[2 * g + 1][1], aBl + off);
            }
#pragma unroll
            for (int mt = 0; mt < 2; mt++)
#pragma unroll
                for (int nt = 0; nt < 8; nt++) {
                    mma16816(d[mt][nt], fAh[mt], fBh[nt]);
                    mma16816(d[mt][nt], fAh[mt], fBl[nt]);
                    mma16816(d[mt][nt], fAl[mt], fBh[nt]);
                }
        }
    }
}

// qkv: C = X Wz^T, epilogue remaps [m,e] -> [b,h,s,dk] (z = blockIdx.z)
__global__ __launch_bounds__(256) void qkv_mma_kernel()
{
    const int z  = blockIdx.z;
    const int m0 = blockIdx.y * 128, n0 = blockIdx.x * 128;
    float d[2][8][4];
    gemm_tile_core(g_Xh, g_Xl, g_Wh[z], g_Wl[z], m0, n0, d);

    float* dst = (z == 0) ? g_q : (z == 1 ? g_k : g_v);
    const int lane = threadIdx.x & 31, wid = threadIdx.x >> 5;
    const int wm = wid >> 1, wn = wid & 1;
#pragma unroll
    for (int mt = 0; mt < 2; mt++) {
        const int r0 = m0 + wm * 32 + mt * 16 + (lane >> 2);
#pragma unroll
        for (int nt = 0; nt < 8; nt++) {
            const int e  = n0 + wn * 64 + nt * 8 + (lane & 3) * 2;
            const int h  = e >> 6, dk = e & 63;
            // rows r0 and r0+8 (same b since tiles never straddle the 2048 boundary)
            const int b = r0 >> 11;
            const int s = r0 & (SEQ - 1);
            float* p0 = dst + (((size_t)b * NHEADS + h) * SEQ + s) * DK + dk;
            *(float2*)p0             = make_float2(d[mt][nt][0], d[mt][nt][1]);
            *(float2*)(p0 + 8 * DK)  = make_float2(d[mt][nt][2], d[mt][nt][3]);
        }
    }
}

// out-proj: out = O Wo^T + bo
__global__ __launch_bounds__(256) void out_mma_kernel(
    const float* __restrict__ bias, float* __restrict__ out)
{
    const int m0 = blockIdx.y * 128, n0 = blockIdx.x * 128;
    float d[2][8][4];
    gemm_tile_core(g_Oh, g_Ol, g_Wh[3], g_Wl[3], m0, n0, d);

    const int lane = threadIdx.x & 31, wid = threadIdx.x >> 5;
    const int wm = wid >> 1, wn = wid & 1;
#pragma unroll
    for (int mt = 0; mt < 2; mt++) {
        const int r0 = m0 + wm * 32 + mt * 16 + (lane >> 2);
#pragma unroll
        for (int nt = 0; nt < 8; nt++) {
            const int e = n0 + wn * 64 + nt * 8 + (lane & 3) * 2;
            const float b0 = bias[e], b1 = bias[e + 1];
            float* p0 = out + (size_t)r0 * DMODEL + e;
            *(float2*)p0                 = make_float2(d[mt][nt][0] + b0, d[mt][nt][1] + b1);
            *(float2*)(p0 + 8 * DMODEL)  = make_float2(d[mt][nt][2] + b0, d[mt][nt][3] + b1);
        }
    }
}

// ===========================================================================
// Causal flash attention (fp32, unchanged — passed R5 with rel_err 6.5e-7)
// ===========================================================================
__global__ __launch_bounds__(256) void attn_kernel()
{
    __shared__ float Qt[64][68];
    __shared__ float Kt[64][34];
    __shared__ float Vs[32][68];
    __shared__ float Pt[32][65];

    const int tid = threadIdx.x;
    const int ty  = tid >> 4;
    const int tx  = tid & 15;
    const int bh  = blockIdx.y;
    const int b   = bh >> 4;
    const int h   = bh & 15;
    const int qt  = (int)gridDim.x - 1 - (int)blockIdx.x;
    const int q0  = qt * 64;

    const float* Qb = g_q + (size_t)bh * SEQ * DK;
    const float* Kb = g_k + (size_t)bh * SEQ * DK;
    const float* Vb = g_v + (size_t)bh * SEQ * DK;

#pragma unroll
    for (int r = 0; r < 16; r++) {
        const int idx = r * 256 + tid;
        const int i = idx >> 6, d = idx & 63;
        Qt[d][i] = Qb[(size_t)(q0 + i) * DK + d];
    }

    float m_i[4], l_i[4], acc[4][4];
#pragma unroll
    for (int i = 0; i < 4; i++) {
        m_i[i] = -1e30f;
        l_i[i] = 0.0f;
#pragma unroll
        for (int j = 0; j < 4; j++) acc[i][j] = 0.0f;
    }

    const int ntiles = (qt + 1) * 2;
    for (int kt = 0; kt < ntiles; kt++) {
        const int k0 = kt * 32;
        __syncthreads();
#pragma unroll
        for (int r = 0; r < 8; r++) {
            const int idx = r * 256 + tid;
            const int j = idx >> 6, d = idx & 63;
            Kt[d][j] = Kb[(size_t)(k0 + j) * DK + d];
            Vs[j][d] = Vb[(size_t)(k0 + j) * DK + d];
        }
        __syncthreads();

        float s0[4] = {0.f, 0.f, 0.f, 0.f};
        float s1[4] = {0.f, 0.f, 0.f, 0.f};
#pragma unroll 16
        for (int d = 0; d < 64; d++) {
            float4 q4 = *(const float4*)&Qt[d][ty * 4];
            float2 k2 = *(const float2*)&Kt[d][tx * 2];
            s0[0] += q4.x * k2.x;  s1[0] += q4.x * k2.y;
            s0[1] += q4.y * k2.x;  s1[1] += q4.y * k2.y;
            s0[2] += q4.z * k2.x;  s1[2] += q4.z * k2.y;
            s0[3] += q4.w * k2.x;  s1[3] += q4.w * k2.y;
        }

        const float sc = 0.125f;
        const bool need_mask = (k0 + 31 > q0);
        const int kc0 = k0 + tx * 2;
        const int kc1 = kc0 + 1;
#pragma unroll
        for (int i = 0; i < 4; i++) {
            float a = s0[i] * sc;
            float c = s1[i] * sc;
            if (need_mask) {
                const int qi = q0 + ty * 4 + i;
                if (kc0 > qi) a = -1e30f;
                if (kc1 > qi) c = -1e30f;
            }
            s0[i] = a; s1[i] = c;
        }

#pragma unroll
        for (int i = 0; i < 4; i++) {
            float mx = fmaxf(s0[i], s1[i]);
            mx = fmaxf(mx, __shfl_xor_sync(0xffffffffu, mx, 1));
            mx = fmaxf(mx, __shfl_xor_sync(0xffffffffu, mx, 2));
            mx = fmaxf(mx, __shfl_xor_sync(0xffffffffu, mx, 4));
            mx = fmaxf(mx, __shfl_xor_sync(0xffffffffu, mx, 8));
            const float m_new = fmaxf(m_i[i], mx);
            const float alpha = __expf(m_i[i] - m_new);
            m_i[i] = m_new;
            const float p0 = __expf(s0[i] - m_new);
            const float p1 = __expf(s1[i] - m_new);
            float rs = p0 + p1;
            rs += __shfl_xor_sync(0xffffffffu, rs, 1);
            rs += __shfl_xor_sync(0xffffffffu, rs, 2);
            rs += __shfl_xor_sync(0xffffffffu, rs, 4);
            rs += __shfl_xor_sync(0xffffffffu, rs, 8);
            l_i[i] = l_i[i] * alpha + rs;
#pragma unroll
            for (int j = 0; j < 4; j++) acc[i][j] *= alpha;
            Pt[tx * 2 + 0][ty * 4 + i] = p0;
            Pt[tx * 2 + 1][ty * 4 + i] = p1;
        }
        __syncthreads();

#pragma unroll 8
        for (int j = 0; j < 32; j++) {
            float4 v4 = *(const float4*)&Vs[j][tx * 4];
            const float pr0 = Pt[j][ty * 4 + 0];
            const float pr1 = Pt[j][ty * 4 + 1];
            const float pr2 = Pt[j][ty * 4 + 2];
            const float pr3 = Pt[j][ty * 4 + 3];
            acc[0][0] += pr0 * v4.x; acc[0][1] += pr0 * v4.y; acc[0][2] += pr0 * v4.z; acc[0][3] += pr0 * v4.w;
            acc[1][0] += pr1 * v4.x; acc[1][1] += pr1 * v4.y; acc[1][2] += pr1 * v4.z; acc[1][3] += pr1 * v4.w;
            acc[2][0] += pr2 * v4.x; acc[2][1] += pr2 * v4.y; acc[2][2] += pr2 * v4.z; acc[2][3] += pr2 * v4.w;
            acc[3][0] += pr3 * v4.x; acc[3][1] += pr3 * v4.y; acc[3][2] += pr3 * v4.z; acc[3][3] += pr3 * v4.w;
        }
    }

#pragma unroll
    for (int i = 0; i < 4; i++) {
        const float inv = 1.0f / l_i[i];
        const int s = q0 + ty * 4 + i;
        const size_t base = (((size_t)b * SEQ + s) * NHEADS + h) * DK + tx * 4;
        g_o[base + 0] = acc[i][0] * inv;
        g_o[base + 1] = acc[i][1] * inv;
        g_o[base + 2] = acc[i][2] * inv;
        g_o[base + 3] = acc[i][3] * inv;
    }
}

// ===========================================================================
extern "C" void kernel_launch(void* const* d_in, const int* in_sizes, int n_in,
                              void* d_out, int out_size)
{
    (void)in_sizes; (void)n_in; (void)out_size;
    const float* x  = (const float*)d_in[0];
    const float* Wq = (const float*)d_in[1];
    const float* Wk = (const float*)d_in[2];
    const float* Wv = (const float*)d_in[3];
    const float* Wo = (const float*)d_in[4];
    const float* bo = (const float*)d_in[5];
    float* out = (float*)d_out;

    const int nX4 = MROWS * DMODEL / 4;    // 1,048,576
    const int nW4 = DMODEL * DMODEL / 4;   //   262,144
    cvt_split_kernel<<<nX4 / 256, 256>>>(x,  0, nX4);
    cvt_split_kernel<<<nW4 / 256, 256>>>(Wq, 1, nW4);
    cvt_split_kernel<<<nW4 / 256, 256>>>(Wk, 2, nW4);
    cvt_split_kernel<<<nW4 / 256, 256>>>(Wv, 3, nW4);
    cvt_split_kernel<<<nW4 / 256, 256>>>(Wo, 4, nW4);

    qkv_mma_kernel<<<dim3(DMODEL / 128, MROWS / 128, 3), 256>>>();
    attn_kernel<<<dim3(SEQ / 64, BATCH * NHEADS), 256>>>();
    cvt_split_kernel<<<nX4 / 256, 256>>>(x, 5, nX4);   // src overridden to g_o
    out_mma_kernel<<<dim3(DMODEL / 128, MROWS / 128), 256>>>(bo, out);
}

// round 9
// speedup vs baseline: 2.4136x; 1.6819x over previous
#include <cuda_runtime.h>
#include <cuda_bf16.h>
#include <math.h>
#include <stdint.h>

#define BATCH   2
#define SEQ     2048
#define DMODEL  1024
#define NHEADS  16
#define DK      64
#define MROWS   (BATCH * SEQ)   // 4096

// -------------------- scratch (__device__ globals; no allocations) ---------
// split-bf16 operands
__device__ __nv_bfloat16 g_Xh[(size_t)MROWS * DMODEL];
__device__ __nv_bfloat16 g_Xl[(size_t)MROWS * DMODEL];
__device__ __nv_bfloat16 g_Wh[4][(size_t)DMODEL * DMODEL];  // q,k,v,o
__device__ __nv_bfloat16 g_Wl[4][(size_t)DMODEL * DMODEL];
// Q/K/V in [b,h,s,dk], split
__device__ __nv_bfloat16 g_qh[(size_t)BATCH * NHEADS * SEQ * DK];
__device__ __nv_bfloat16 g_ql[(size_t)BATCH * NHEADS * SEQ * DK];
__device__ __nv_bfloat16 g_kh[(size_t)BATCH * NHEADS * SEQ * DK];
__device__ __nv_bfloat16 g_kl[(size_t)BATCH * NHEADS * SEQ * DK];
__device__ __nv_bfloat16 g_vh[(size_t)BATCH * NHEADS * SEQ * DK];
__device__ __nv_bfloat16 g_vl[(size_t)BATCH * NHEADS * SEQ * DK];
// attention output (concat layout [b,s,h*dk] = [m,d]), split
__device__ __nv_bfloat16 g_Oh[(size_t)MROWS * DMODEL];
__device__ __nv_bfloat16 g_Ol[(size_t)MROWS * DMODEL];

// ===========================================================================
// warp-MMA helpers (arch-portable sm_80+ ISA; tcgen05 rejected by the
// harness's compute_103 virtual-arch build)
// ===========================================================================
__device__ __forceinline__ uint32_t smem_u32(const void* p) {
    uint32_t a;
    asm("{ .reg .u64 t; cvta.to.shared.u64 t, %1; cvt.u32.u64 %0, t; }"
        : "=r"(a) : "l"(p));
    return a;
}

__device__ __forceinline__ void ldsm_x4(uint32_t& r0, uint32_t& r1,
                                        uint32_t& r2, uint32_t& r3, uint32_t addr) {
    asm volatile("ldmatrix.sync.aligned.m8n8.x4.shared.b16 {%0,%1,%2,%3}, [%4];"
                 : "=r"(r0), "=r"(r1), "=r"(r2), "=r"(r3) : "r"(addr));
}

__device__ __forceinline__ void ldsm_x4t(uint32_t& r0, uint32_t& r1,
                                         uint32_t& r2, uint32_t& r3, uint32_t addr) {
    asm volatile("ldmatrix.sync.aligned.m8n8.x4.trans.shared.b16 {%0,%1,%2,%3}, [%4];"
                 : "=r"(r0), "=r"(r1), "=r"(r2), "=r"(r3) : "r"(addr));
}

__device__ __forceinline__ void mma16816(float* d, const uint32_t* a, const uint32_t* b) {
    asm volatile(
        "mma.sync.aligned.m16n8k16.row.col.f32.bf16.bf16.f32 "
        "{%0,%1,%2,%3}, {%4,%5,%6,%7}, {%8,%9}, {%0,%1,%2,%3};"
        : "+f"(d[0]), "+f"(d[1]), "+f"(d[2]), "+f"(d[3])
        : "r"(a[0]), "r"(a[1]), "r"(a[2]), "r"(a[3]), "r"(b[0]), "r"(b[1]));
}

// split a pair of fp32 into packed bf16x2 (hi) + packed bf16x2 (lo residual)
__device__ __forceinline__ void split2(float x, float y, uint32_t& hi, uint32_t& lo) {
    __nv_bfloat162 H, L;
    H.x = __float2bfloat16(x);
    H.y = __float2bfloat16(y);
    L.x = __float2bfloat16(x - __bfloat162float(H.x));
    L.y = __float2bfloat16(y - __bfloat162float(H.y));
    hi = *(uint32_t*)&H;
    lo = *(uint32_t*)&L;
}

// ===========================================================================
// fp32 -> (hi, lo) bf16 split.  which: 0=X, 1..4=Wq/Wk/Wv/Wo
// ===========================================================================
__global__ void cvt_split_kernel(const float* __restrict__ src, int which, int n4)
{
    int i = blockIdx.x * blockDim.x + threadIdx.x;
    if (i >= n4) return;
    __nv_bfloat16 *hi, *lo;
    switch (which) {
        case 1:  hi = g_Wh[0]; lo = g_Wl[0]; break;
        case 2:  hi = g_Wh[1]; lo = g_Wl[1]; break;
        case 3:  hi = g_Wh[2]; lo = g_Wl[2]; break;
        case 4:  hi = g_Wh[3]; lo = g_Wl[3]; break;
        default: hi = g_Xh;    lo = g_Xl;    break;
    }
    float4 v = ((const float4*)src)[i];
    uint32_t h0, h1, l0, l1;
    split2(v.x, v.y, h0, l0);
    split2(v.z, v.w, h1, l1);
    ((uint32_t*)hi)[2 * i + 0] = h0;
    ((uint32_t*)hi)[2 * i + 1] = h1;
    ((uint32_t*)lo)[2 * i + 0] = l0;
    ((uint32_t*)lo)[2 * i + 1] = l1;
}

// ===========================================================================
// Split-bf16 GEMM core: C[128,128] = A[128,K] · B[128,K]^T (hh + hl + lh),
// m16n8k16 MMA. 256 threads, warp grid 4(m) x 2(n).
// ===========================================================================
#define SA 40   // smem row stride in bf16 elems (80B -> 8 distinct 16B phases)

__device__ __forceinline__ void gemm_tile_core(
    const __nv_bfloat16* __restrict__ Ah, const __nv_bfloat16* __restrict__ Al,
    const __nv_bfloat16* __restrict__ Bh, const __nv_bfloat16* __restrict__ Bl,
    int m0, int n0, float d[2][8][4])
{
    __shared__ __nv_bfloat16 sAh[128 * SA], sAl[128 * SA];
    __shared__ __nv_bfloat16 sBh[128 * SA], sBl[128 * SA];

    const int tid  = threadIdx.x;
    const int lane = tid & 31;
    const int wid  = tid >> 5;
    const int wm   = wid >> 1;
    const int wn   = wid & 1;

    const uint32_t aAh = smem_u32(sAh), aAl = smem_u32(sAl);
    const uint32_t aBh = smem_u32(sBh), aBl = smem_u32(sBl);

    const int sub  = lane >> 3, l7 = lane & 7;
    const int arow = wm * 32 + l7 + (sub & 1) * 8;
    const int akof = (sub >> 1) * 8;
    const int brow = wn * 64 + l7 + (sub >> 1) * 8;
    const int bkof = (sub & 1) * 8;

    const int grow = tid >> 2;
    const int gq   = (tid & 3) * 8;

#pragma unroll
    for (int mt = 0; mt < 2; mt++)
#pragma unroll
        for (int nt = 0; nt < 8; nt++)
#pragma unroll
            for (int c = 0; c < 4; c++) d[mt][nt][c] = 0.0f;

    uint4 va[2][4];
#pragma unroll
    for (int p = 0; p < 2; p++) {
        const size_t ga = (size_t)(m0 + p * 64 + grow) * DMODEL + gq;
        const size_t gb = (size_t)(n0 + p * 64 + grow) * DMODEL + gq;
        va[p][0] = *(const uint4*)(Ah + ga);
        va[p][1] = *(const uint4*)(Al + ga);
        va[p][2] = *(const uint4*)(Bh + gb);
        va[p][3] = *(const uint4*)(Bl + gb);
    }

    for (int it = 0; it < DMODEL / 32; it++) {
        __syncthreads();
#pragma unroll
        for (int p = 0; p < 2; p++) {
            const int so = (p * 64 + grow) * SA + gq;
            *(uint4*)(sAh + so) = va[p][0];
            *(uint4*)(sAl + so) = va[p][1];
            *(uint4*)(sBh + so) = va[p][2];
            *(uint4*)(sBl + so) = va[p][3];
        }
        if (it + 1 < DMODEL / 32) {
            const int k0 = (it + 1) * 32;
#pragma unroll
            for (int p = 0; p < 2; p++) {
                const size_t ga = (size_t)(m0 + p * 64 + grow) * DMODEL + k0 + gq;
                const size_t gb = (size_t)(n0 + p * 64 + grow) * DMODEL + k0 + gq;
                va[p][0] = *(const uint4*)(Ah + ga);
                va[p][1] = *(const uint4*)(Al + ga);
                va[p][2] = *(const uint4*)(Bh + gb);
                va[p][3] = *(const uint4*)(Bl + gb);
            }
        }
        __syncthreads();

#pragma unroll
        for (int s = 0; s < 2; s++) {
            const int ks = s * 16;
            uint32_t fAh[2][4], fAl[2][4], fBh[8][2], fBl[8][2];
#pragma unroll
            for (int mt = 0; mt < 2; mt++) {
                const uint32_t off = ((arow + mt * 16) * SA + ks + akof) * 2;
                ldsm_x4(fAh[mt][0], fAh[mt][1], fAh[mt][2], fAh[mt][3], aAh + off);
                ldsm_x4(fAl[mt][0], fAl[mt][1], fAl[mt][2], fAl[mt][3], aAl + off);
            }
#pragma unroll
            for (int g = 0; g < 4; g++) {
                const uint32_t off = ((brow + g * 16) * SA + ks + bkof) * 2;
                ldsm_x4(fBh[2 * g][0], fBh[2 * g][1], fBh[2 * g + 1][0], fBh[2 * g + 1][1], aBh + off);
                ldsm_x4(fBl[2 * g][0], fBl[2 * g][1], fBl[2 * g + 1][0], fBl[2 * g + 1][1], aBl + off);
            }
#pragma unroll
            for (int mt = 0; mt < 2; mt++)
#pragma unroll
                for (int nt = 0; nt < 8; nt++) {
                    mma16816(d[mt][nt], fAh[mt], fBh[nt]);
                    mma16816(d[mt][nt], fAh[mt], fBl[nt]);
                    mma16816(d[mt][nt], fAl[mt], fBh[nt]);
                }
        }
    }
}

// qkv: C = X Wz^T, epilogue splits to bf16 hi/lo in [b,h,s,dk]
__global__ __launch_bounds__(256) void qkv_mma_kernel()
{
    const int z  = blockIdx.z;
    const int m0 = blockIdx.y * 128, n0 = blockIdx.x * 128;
    float d[2][8][4];
    gemm_tile_core(g_Xh, g_Xl, g_Wh[z], g_Wl[z], m0, n0, d);

    __nv_bfloat16* dh = (z == 0) ? g_qh : (z == 1 ? g_kh : g_vh);
    __nv_bfloat16* dl = (z == 0) ? g_ql : (z == 1 ? g_kl : g_vl);
    const int lane = threadIdx.x & 31, wid = threadIdx.x >> 5;
    const int wm = wid >> 1, wn = wid & 1;
#pragma unroll
    for (int mt = 0; mt < 2; mt++) {
        const int r0 = m0 + wm * 32 + mt * 16 + (lane >> 2);
        const int b = r0 >> 11;
        const int s = r0 & (SEQ - 1);
#pragma unroll
        for (int nt = 0; nt < 8; nt++) {
            const int e  = n0 + wn * 64 + nt * 8 + (lane & 3) * 2;
            const int h  = e >> 6, dk = e & 63;
            const size_t i0 = (((size_t)b * NHEADS + h) * SEQ + s) * DK + dk;
            uint32_t hi, lo;
            split2(d[mt][nt][0], d[mt][nt][1], hi, lo);
            *(uint32_t*)(dh + i0) = hi;
            *(uint32_t*)(dl + i0) = lo;
            split2(d[mt][nt][2], d[mt][nt][3], hi, lo);
            *(uint32_t*)(dh + i0 + 8 * DK) = hi;   // row s+8
            *(uint32_t*)(dl + i0 + 8 * DK) = lo;
        }
    }
}

// out-proj: out = O Wo^T + bo
__global__ __launch_bounds__(256) void out_mma_kernel(
    const float* __restrict__ bias, float* __restrict__ out)
{
    const int m0 = blockIdx.y * 128, n0 = blockIdx.x * 128;
    float d[2][8][4];
    gemm_tile_core(g_Oh, g_Ol, g_Wh[3], g_Wl[3], m0, n0, d);

    const int lane = threadIdx.x & 31, wid = threadIdx.x >> 5;
    const int wm = wid >> 1, wn = wid & 1;
#pragma unroll
    for (int mt = 0; mt < 2; mt++) {
        const int r0 = m0 + wm * 32 + mt * 16 + (lane >> 2);
#pragma unroll
        for (int nt = 0; nt < 8; nt++) {
            const int e = n0 + wn * 64 + nt * 8 + (lane & 3) * 2;
            const float b0 = bias[e], b1 = bias[e + 1];
            float* p0 = out + (size_t)r0 * DMODEL + e;
            *(float2*)p0                 = make_float2(d[mt][nt][0] + b0, d[mt][nt][1] + b1);
            *(float2*)(p0 + 8 * DMODEL)  = make_float2(d[mt][nt][2] + b0, d[mt][nt][3] + b1);
        }
    }
}

// ===========================================================================
// Tensor-core causal flash attention, split-bf16 (3-pass) on both GEMMs.
// CTA: 128 q-rows, 8 warps x 16 rows; BN=64 keys/iter; DK=64.
// Softmax rows live in one warp (4-lane shfl reductions). P stays in regs
// (S C-fragment == PV A-fragment layout). V fragments via ldmatrix.trans.
// ===========================================================================
#define ASA 72   // smem row stride (144B -> 8 distinct 16B phases)

__global__ __launch_bounds__(256) void attn_mma_kernel()
{
    __shared__ __nv_bfloat16 sm[256 * ASA];   // 36,864 B
    // layout mainloop: Kh @0, Kl @64*ASA, Vh @128*ASA, Vl @192*ASA (rows=key)
    // layout prologue: Qh rows 0..127 @0, Ql rows 0..127 @128*ASA

    const int tid  = threadIdx.x;
    const int lane = tid & 31;
    const int w    = tid >> 5;
    const int bh   = blockIdx.y;
    const int b    = bh >> 4, h = bh & 15;
    const int qt   = (int)gridDim.x - 1 - (int)blockIdx.x;   // heavy first
    const int q0   = qt * 128;

    const __nv_bfloat16* Qh = g_qh + (size_t)bh * SEQ * DK;
    const __nv_bfloat16* Ql = g_ql + (size_t)bh * SEQ * DK;
    const __nv_bfloat16* Kh = g_kh + (size_t)bh * SEQ * DK;
    const __nv_bfloat16* Kl = g_kl + (size_t)bh * SEQ * DK;
    const __nv_bfloat16* Vh = g_vh + (size_t)bh * SEQ * DK;
    const __nv_bfloat16* Vl = g_vl + (size_t)bh * SEQ * DK;

    const uint32_t sb = smem_u32(sm);
    const int sub = lane >> 3, l7 = lane & 7;

    // ---- prologue: stage Q tile, pull A fragments into registers ----------
    uint32_t qfh[4][4], qfl[4][4];
    {
#pragma unroll
        for (int v = 0; v < 4; v++) {
            const int item = v * 256 + tid;         // 0..1023
            const int row = item >> 3, sec = item & 7;
            const size_t gi = (size_t)(q0 + row) * DK + sec * 8;
            *(uint4*)(sm + row * ASA + sec * 8)             = *(const uint4*)(Qh + gi);
            *(uint4*)(sm + 128 * ASA + row * ASA + sec * 8) = *(const uint4*)(Ql + gi);
        }
        __syncthreads();
        const int arow = w * 16 + l7 + (sub & 1) * 8;
        const int akof = (sub >> 1) * 8;
#pragma unroll
        for (int ks = 0; ks < 4; ks++) {
            const uint32_t off = (uint32_t)(arow * ASA + ks * 16 + akof) * 2;
            ldsm_x4(qfh[ks][0], qfh[ks][1], qfh[ks][2], qfh[ks][3], sb + off);
            ldsm_x4(qfl[ks][0], qfl[ks][1], qfl[ks][2], qfl[ks][3], sb + 128 * ASA * 2 + off);
        }
        __syncthreads();
    }

    float o[8][4];
#pragma unroll
    for (int nt = 0; nt < 8; nt++)
#pragma unroll
        for (int c = 0; c < 4; c++) o[nt][c] = 0.0f;
    float m0r = -1e30f, m1r = -1e30f, l0r = 0.0f, l1r = 0.0f;

    const int g    = lane >> 2;              // row group within warp tile
    const int r0   = q0 + w * 16 + g;        // global q row (and r0+8)
    const int cpair = (lane & 3) * 2;

    const int ntiles = qt * 2 + 2;           // keys [0, q0+128)
    const int ldrow = tid >> 3, ldsec = tid & 7;   // wait: 2 items/thread below

    uint4 va[2][4];
    {
#pragma unroll
        for (int v = 0; v < 2; v++) {
            const int item = v * 256 + tid;
            const int row = item >> 3, sec = item & 7;
            const size_t gi = (size_t)row * DK + sec * 8;
            va[v][0] = *(const uint4*)(Kh + gi);
            va[v][1] = *(const uint4*)(Kl + gi);
            va[v][2] = *(const uint4*)(Vh + gi);
            va[v][3] = *(const uint4*)(Vl + gi);
        }
    }
    (void)ldrow; (void)ldsec;

    for (int kt = 0; kt < ntiles; kt++) {
        const int k0 = kt * 64;
        __syncthreads();
#pragma unroll
        for (int v = 0; v < 2; v++) {
            const int item = v * 256 + tid;
            const int row = item >> 3, sec = item & 7;
            const int so = row * ASA + sec * 8;
            *(uint4*)(sm + so)             = va[v][0];
            *(uint4*)(sm + 64 * ASA + so)  = va[v][1];
            *(uint4*)(sm + 128 * ASA + so) = va[v][2];
            *(uint4*)(sm + 192 * ASA + so) = va[v][3];
        }
        if (kt + 1 < ntiles) {
            const int nk0 = k0 + 64;
#pragma unroll
            for (int v = 0; v < 2; v++) {
                const int item = v * 256 + tid;
                const int row = item >> 3, sec = item & 7;
                const size_t gi = (size_t)(nk0 + row) * DK + sec * 8;
                va[v][0] = *(const uint4*)(Kh + gi);
                va[v][1] = *(const uint4*)(Kl + gi);
                va[v][2] = *(const uint4*)(Vh + gi);
                va[v][3] = *(const uint4*)(Vl + gi);
            }
        }
        __syncthreads();

        // ---- S = Q K^T  (warp tile 16 x 64) -------------------------------
        float d[8][4];
#pragma unroll
        for (int nt = 0; nt < 8; nt++)
#pragma unroll
            for (int c = 0; c < 4; c++) d[nt][c] = 0.0f;

        const int brow = l7 + (sub >> 1) * 8;
        const int bkof = (sub & 1) * 8;
#pragma unroll
        for (int ks = 0; ks < 4; ks++) {
            uint32_t fh[8][2], fl[8][2];
#pragma unroll
            for (int g2 = 0; g2 < 4; g2++) {
                const uint32_t off = (uint32_t)((g2 * 16 + brow) * ASA + ks * 16 + bkof) * 2;
                ldsm_x4(fh[2 * g2][0], fh[2 * g2][1], fh[2 * g2 + 1][0], fh[2 * g2 + 1][1], sb + off);
                ldsm_x4(fl[2 * g2][0], fl[2 * g2][1], fl[2 * g2 + 1][0], fl[2 * g2 + 1][1], sb + 64 * ASA * 2 + off);
            }
#pragma unroll
            for (int nt = 0; nt < 8; nt++) {
                mma16816(d[nt], qfh[ks], fh[nt]);
                mma16816(d[nt], qfh[ks], fl[nt]);
                mma16816(d[nt], qfl[ks], fh[nt]);
            }
        }

        // ---- scale + causal mask ------------------------------------------
        const float sc = 0.125f;
        const bool need_mask = (k0 + 63 > q0 + w * 16);
#pragma unroll
        for (int nt = 0; nt < 8; nt++) {
            const int key0 = k0 + nt * 8 + cpair;
            float v0 = d[nt][0] * sc, v1 = d[nt][1] * sc;
            float v2 = d[nt][2] * sc, v3 = d[nt][3] * sc;
            if (need_mask) {
                if (key0     > r0)     v0 = -1e30f;
                if (key0 + 1 > r0)     v1 = -1e30f;
                if (key0     > r0 + 8) v2 = -1e30f;
                if (key0 + 1 > r0 + 8) v3 = -1e30f;
            }
            d[nt][0] = v0; d[nt][1] = v1; d[nt][2] = v2; d[nt][3] = v3;
        }

        // ---- online softmax (rows r0, r0+8) -------------------------------
        float mx0 = -1e30f, mx1 = -1e30f;
#pragma unroll
        for (int nt = 0; nt < 8; nt++) {
            mx0 = fmaxf(mx0, fmaxf(d[nt][0], d[nt][1]));
            mx1 = fmaxf(mx1, fmaxf(d[nt][2], d[nt][3]));
        }
        mx0 = fmaxf(mx0, __shfl_xor_sync(0xffffffffu, mx0, 1));
        mx0 = fmaxf(mx0, __shfl_xor_sync(0xffffffffu, mx0, 2));
        mx1 = fmaxf(mx1, __shfl_xor_sync(0xffffffffu, mx1, 1));
        mx1 = fmaxf(mx1, __shfl_xor_sync(0xffffffffu, mx1, 2));

        const float mn0 = fmaxf(m0r, mx0);
        const float mn1 = fmaxf(m1r, mx1);
        const float a0 = __expf(m0r - mn0);
        const float a1 = __expf(m1r - mn1);
        m0r = mn0; m1r = mn1;

        float rs0 = 0.0f, rs1 = 0.0f;
#pragma unroll
        for (int nt = 0; nt < 8; nt++) {
            d[nt][0] = __expf(d[nt][0] - mn0);
            d[nt][1] = __expf(d[nt][1] - mn0);
            d[nt][2] = __expf(d[nt][2] - mn1);
            d[nt][3] = __expf(d[nt][3] - mn1);
            rs0 += d[nt][0] + d[nt][1];
            rs1 += d[nt][2] + d[nt][3];
        }
        rs0 += __shfl_xor_sync(0xffffffffu, rs0, 1);
        rs0 += __shfl_xor_sync(0xffffffffu, rs0, 2);
        rs1 += __shfl_xor_sync(0xffffffffu, rs1, 1);
        rs1 += __shfl_xor_sync(0xffffffffu, rs1, 2);
        l0r = l0r * a0 + rs0;
        l1r = l1r * a1 + rs1;

#pragma unroll
        for (int nt = 0; nt < 8; nt++) {
            o[nt][0] *= a0; o[nt][1] *= a0;
            o[nt][2] *= a1; o[nt][3] *= a1;
        }

        // ---- O += P V  (P from regs; V via ldmatrix.trans) ----------------
#pragma unroll
        for (int kst = 0; kst < 4; kst++) {
            uint32_t pah[4], pal[4];
            split2(d[2 * kst][0],     d[2 * kst][1],     pah[0], pal[0]);
            split2(d[2 * kst][2],     d[2 * kst][3],     pah[1], pal[1]);
            split2(d[2 * kst + 1][0], d[2 * kst + 1][1], pah[2], pal[2]);
            split2(d[2 * kst + 1][2], d[2 * kst + 1][3], pah[3], pal[3]);
            const int vrow = kst * 16 + l7 + (sub & 1) * 8;
            const int vkof = (sub >> 1) * 8;
#pragma unroll
            for (int g2 = 0; g2 < 4; g2++) {
                uint32_t vh[4], vl[4];
                const uint32_t off = (uint32_t)(vrow * ASA + g2 * 16 + vkof) * 2;
                ldsm_x4t(vh[0], vh[1], vh[2], vh[3], sb + 128 * ASA * 2 + off);
                ldsm_x4t(vl[0], vl[1], vl[2], vl[3], sb + 192 * ASA * 2 + off);
                mma16816(o[2 * g2],     pah, &vh[0]);
                mma16816(o[2 * g2],     pah, &vl[0]);
                mma16816(o[2 * g2],     pal, &vh[0]);
                mma16816(o[2 * g2 + 1], pah, &vh[2]);
                mma16816(o[2 * g2 + 1], pah, &vl[2]);
                mma16816(o[2 * g2 + 1], pal, &vh[2]);
            }
        }
    }

    // ---- epilogue: normalize, split to bf16 hi/lo in [b,s,h*dk] -----------
    const float i0 = 1.0f / l0r;
    const float i1 = 1.0f / l1r;
#pragma unroll
    for (int nt = 0; nt < 8; nt++) {
        const int dkc = h * 64 + nt * 8 + cpair;
        const size_t idx = ((size_t)b * SEQ + r0) * DMODEL + dkc;
        uint32_t hi, lo;
        split2(o[nt][0] * i0, o[nt][1] * i0, hi, lo);
        *(uint32_t*)(g_Oh + idx) = hi;
        *(uint32_t*)(g_Ol + idx) = lo;
        split2(o[nt][2] * i1, o[nt][3] * i1, hi, lo);
        *(uint32_t*)(g_Oh + idx + 8 * DMODEL) = hi;   // row r0+8
        *(uint32_t*)(g_Ol + idx + 8 * DMODEL) = lo;
    }
}

// ===========================================================================
extern "C" void kernel_launch(void* const* d_in, const int* in_sizes, int n_in,
                              void* d_out, int out_size)
{
    (void)in_sizes; (void)n_in; (void)out_size;
    const float* x  = (const float*)d_in[0];
    const float* Wq = (const float*)d_in[1];
    const float* Wk = (const float*)d_in[2];
    const float* Wv = (const float*)d_in[3];
    const float* Wo = (const float*)d_in[4];
    const float* bo = (const float*)d_in[5];
    float* out = (float*)d_out;

    const int nX4 = MROWS * DMODEL / 4;
    const int nW4 = DMODEL * DMODEL / 4;
    cvt_split_kernel<<<nX4 / 256, 256>>>(x,  0, nX4);
    cvt_split_kernel<<<nW4 / 256, 256>>>(Wq, 1, nW4);
    cvt_split_kernel<<<nW4 / 256, 256>>>(Wk, 2, nW4);
    cvt_split_kernel<<<nW4 / 256, 256>>>(Wv, 3, nW4);
    cvt_split_kernel<<<nW4 / 256, 256>>>(Wo, 4, nW4);

    qkv_mma_kernel<<<dim3(DMODEL / 128, MROWS / 128, 3), 256>>>();
    attn_mma_kernel<<<dim3(SEQ / 128, BATCH * NHEADS), 256>>>();
    out_mma_kernel<<<dim3(DMODEL / 128, MROWS / 128), 256>>>(bo, out);
}

// round 10
// speedup vs baseline: 2.4853x; 1.0297x over previous
#include <cuda_runtime.h>
#include <cuda_bf16.h>
#include <math.h>
#include <stdint.h>

#define BATCH   2
#define SEQ     2048
#define DMODEL  1024
#define NHEADS  16
#define DK      64
#define MROWS   (BATCH * SEQ)   // 4096

// -------------------- scratch (__device__ globals; no allocations) ---------
__device__ __nv_bfloat16 g_Xh[(size_t)MROWS * DMODEL];
__device__ __nv_bfloat16 g_Xl[(size_t)MROWS * DMODEL];
__device__ __nv_bfloat16 g_Wh[4][(size_t)DMODEL * DMODEL];  // q,k,v,o
__device__ __nv_bfloat16 g_Wl[4][(size_t)DMODEL * DMODEL];
__device__ __nv_bfloat16 g_qh[(size_t)BATCH * NHEADS * SEQ * DK];
__device__ __nv_bfloat16 g_ql[(size_t)BATCH * NHEADS * SEQ * DK];
__device__ __nv_bfloat16 g_kh[(size_t)BATCH * NHEADS * SEQ * DK];
__device__ __nv_bfloat16 g_kl[(size_t)BATCH * NHEADS * SEQ * DK];
__device__ __nv_bfloat16 g_vh[(size_t)BATCH * NHEADS * SEQ * DK];
__device__ __nv_bfloat16 g_vl[(size_t)BATCH * NHEADS * SEQ * DK];
__device__ __nv_bfloat16 g_Oh[(size_t)MROWS * DMODEL];
__device__ __nv_bfloat16 g_Ol[(size_t)MROWS * DMODEL];

// ===========================================================================
// warp-MMA helpers (arch-portable sm_80+ ISA)
// ===========================================================================
__device__ __forceinline__ uint32_t smem_u32(const void* p) {
    uint32_t a;
    asm("{ .reg .u64 t; cvta.to.shared.u64 t, %1; cvt.u32.u64 %0, t; }"
        : "=r"(a) : "l"(p));
    return a;
}

__device__ __forceinline__ void ldsm_x4(uint32_t& r0, uint32_t& r1,
                                        uint32_t& r2, uint32_t& r3, uint32_t addr) {
    asm volatile("ldmatrix.sync.aligned.m8n8.x4.shared.b16 {%0,%1,%2,%3}, [%4];"
                 : "=r"(r0), "=r"(r1), "=r"(r2), "=r"(r3) : "r"(addr));
}

__device__ __forceinline__ void ldsm_x4t(uint32_t& r0, uint32_t& r1,
                                         uint32_t& r2, uint32_t& r3, uint32_t addr) {
    asm volatile("ldmatrix.sync.aligned.m8n8.x4.trans.shared.b16 {%0,%1,%2,%3}, [%4];"
                 : "=r"(r0), "=r"(r1), "=r"(r2), "=r"(r3) : "r"(addr));
}

__device__ __forceinline__ void mma16816(float* d, const uint32_t* a, const uint32_t* b) {
    asm volatile(
        "mma.sync.aligned.m16n8k16.row.col.f32.bf16.bf16.f32 "
        "{%0,%1,%2,%3}, {%4,%5,%6,%7}, {%8,%9}, {%0,%1,%2,%3};"
        : "+f"(d[0]), "+f"(d[1]), "+f"(d[2]), "+f"(d[3])
        : "r"(a[0]), "r"(a[1]), "r"(a[2]), "r"(a[3]), "r"(b[0]), "r"(b[1]));
}

__device__ __forceinline__ float ex2f(float x) {
    float r;
    asm("ex2.approx.f32 %0, %1;" : "=f"(r) : "f"(x));
    return r;
}

// split pair of fp32 -> packed bf16x2 hi + packed bf16x2 lo residual (6 instr)
__device__ __forceinline__ void split2(float x, float y, uint32_t& hi, uint32_t& lo) {
    uint32_t h;
    asm("cvt.rn.bf16x2.f32 %0, %1, %2;" : "=r"(h) : "f"(y), "f"(x));  // lo16=x, hi16=y
    const float hx = __uint_as_float(h << 16);
    const float hy = __uint_as_float(h & 0xFFFF0000u);
    const float rx = x - hx, ry = y - hy;
    uint32_t l;
    asm("cvt.rn.bf16x2.f32 %0, %1, %2;" : "=r"(l) : "f"(ry), "f"(rx));
    hi = h; lo = l;
}

// ===========================================================================
// fp32 -> (hi, lo) bf16 split.  which: 0=X, 1..4=Wq/Wk/Wv/Wo
// ===========================================================================
__global__ void cvt_split_kernel(const float* __restrict__ src, int which, int n4)
{
    int i = blockIdx.x * blockDim.x + threadIdx.x;
    if (i >= n4) return;
    __nv_bfloat16 *hi, *lo;
    switch (which) {
        case 1:  hi = g_Wh[0]; lo = g_Wl[0]; break;
        case 2:  hi = g_Wh[1]; lo = g_Wl[1]; break;
        case 3:  hi = g_Wh[2]; lo = g_Wl[2]; break;
        case 4:  hi = g_Wh[3]; lo = g_Wl[3]; break;
        default: hi = g_Xh;    lo = g_Xl;    break;
    }
    float4 v = ((const float4*)src)[i];
    uint32_t h0, h1, l0, l1;
    split2(v.x, v.y, h0, l0);
    split2(v.z, v.w, h1, l1);
    ((uint2*)hi)[i] = make_uint2(h0, h1);
    ((uint2*)lo)[i] = make_uint2(l0, l1);
}

// ===========================================================================
// Split-bf16 GEMM core (UNCHANGED from R9 — measured at the HMMA ceiling).
// ===========================================================================
#define SA 40

__device__ __forceinline__ void gemm_tile_core(
    const __nv_bfloat16* __restrict__ Ah, const __nv_bfloat16* __restrict__ Al,
    const __nv_bfloat16* __restrict__ Bh, const __nv_bfloat16* __restrict__ Bl,
    int m0, int n0, float d[2][8][4])
{
    __shared__ __nv_bfloat16 sAh[128 * SA], sAl[128 * SA];
    __shared__ __nv_bfloat16 sBh[128 * SA], sBl[128 * SA];

    const int tid  = threadIdx.x;
    const int lane = tid & 31;
    const int wid  = tid >> 5;
    const int wm   = wid >> 1;
    const int wn   = wid & 1;

    const uint32_t aAh = smem_u32(sAh), aAl = smem_u32(sAl);
    const uint32_t aBh = smem_u32(sBh), aBl = smem_u32(sBl);

    const int sub  = lane >> 3, l7 = lane & 7;
    const int arow = wm * 32 + l7 + (sub & 1) * 8;
    const int akof = (sub >> 1) * 8;
    const int brow = wn * 64 + l7 + (sub >> 1) * 8;
    const int bkof = (sub & 1) * 8;

    const int grow = tid >> 2;
    const int gq   = (tid & 3) * 8;

#pragma unroll
    for (int mt = 0; mt < 2; mt++)
#pragma unroll
        for (int nt = 0; nt < 8; nt++)
#pragma unroll
            for (int c = 0; c < 4; c++) d[mt][nt][c] = 0.0f;

    uint4 va[2][4];
#pragma unroll
    for (int p = 0; p < 2; p++) {
        const size_t ga = (size_t)(m0 + p * 64 + grow) * DMODEL + gq;
        const size_t gb = (size_t)(n0 + p * 64 + grow) * DMODEL + gq;
        va[p][0] = *(const uint4*)(Ah + ga);
        va[p][1] = *(const uint4*)(Al + ga);
        va[p][2] = *(const uint4*)(Bh + gb);
        va[p][3] = *(const uint4*)(Bl + gb);
    }

    for (int it = 0; it < DMODEL / 32; it++) {
        __syncthreads();
#pragma unroll
        for (int p = 0; p < 2; p++) {
            const int so = (p * 64 + grow) * SA + gq;
            *(uint4*)(sAh + so) = va[p][0];
            *(uint4*)(sAl + so) = va[p][1];
            *(uint4*)(sBh + so) = va[p][2];
            *(uint4*)(sBl + so) = va[p][3];
        }
        if (it + 1 < DMODEL / 32) {
            const int k0 = (it + 1) * 32;
#pragma unroll
            for (int p = 0; p < 2; p++) {
                const size_t ga = (size_t)(m0 + p * 64 + grow) * DMODEL + k0 + gq;
                const size_t gb = (size_t)(n0 + p * 64 + grow) * DMODEL + k0 + gq;
                va[p][0] = *(const uint4*)(Ah + ga);
                va[p][1] = *(const uint4*)(Al + ga);
                va[p][2] = *(const uint4*)(Bh + gb);
                va[p][3] = *(const uint4*)(Bl + gb);
            }
        }
        __syncthreads();

#pragma unroll
        for (int s = 0; s < 2; s++) {
            const int ks = s * 16;
            uint32_t fAh[2][4], fAl[2][4], fBh[8][2], fBl[8][2];
#pragma unroll
            for (int mt = 0; mt < 2; mt++) {
                const uint32_t off = ((arow + mt * 16) * SA + ks + akof) * 2;
                ldsm_x4(fAh[mt][0], fAh[mt][1], fAh[mt][2], fAh[mt][3], aAh + off);
                ldsm_x4(fAl[mt][0], fAl[mt][1], fAl[mt][2], fAl[mt][3], aAl + off);
            }
#pragma unroll
            for (int g = 0; g < 4; g++) {
                const uint32_t off = ((brow + g * 16) * SA + ks + bkof) * 2;
                ldsm_x4(fBh[2 * g][0], fBh[2 * g][1], fBh[2 * g + 1][0], fBh[2 * g + 1][1], aBh + off);
                ldsm_x4(fBl[2 * g][0], fBl[2 * g][1], fBl[2 * g + 1][0], fBl[2 * g + 1][1], aBl + off);
            }
#pragma unroll
            for (int mt = 0; mt < 2; mt++)
#pragma unroll
                for (int nt = 0; nt < 8; nt++) {
                    mma16816(d[mt][nt], fAh[mt], fBh[nt]);
                    mma16816(d[mt][nt], fAh[mt], fBl[nt]);
                    mma16816(d[mt][nt], fAl[mt], fBh[nt]);
                }
        }
    }
}

__global__ __launch_bounds__(256) void qkv_mma_kernel()
{
    const int z  = blockIdx.z;
    const int m0 = blockIdx.y * 128, n0 = blockIdx.x * 128;
    float d[2][8][4];
    gemm_tile_core(g_Xh, g_Xl, g_Wh[z], g_Wl[z], m0, n0, d);

    __nv_bfloat16* dh = (z == 0) ? g_qh : (z == 1 ? g_kh : g_vh);
    __nv_bfloat16* dl = (z == 0) ? g_ql : (z == 1 ? g_kl : g_vl);
    const int lane = threadIdx.x & 31, wid = threadIdx.x >> 5;
    const int wm = wid >> 1, wn = wid & 1;
#pragma unroll
    for (int mt = 0; mt < 2; mt++) {
        const int r0 = m0 + wm * 32 + mt * 16 + (lane >> 2);
        const int b = r0 >> 11;
        const int s = r0 & (SEQ - 1);
#pragma unroll
        for (int nt = 0; nt < 8; nt++) {
            const int e  = n0 + wn * 64 + nt * 8 + (lane & 3) * 2;
            const int h  = e >> 6, dk = e & 63;
            const size_t i0 = (((size_t)b * NHEADS + h) * SEQ + s) * DK + dk;
            uint32_t hi, lo;
            split2(d[mt][nt][0], d[mt][nt][1], hi, lo);
            *(uint32_t*)(dh + i0) = hi;
            *(uint32_t*)(dl + i0) = lo;
            split2(d[mt][nt][2], d[mt][nt][3], hi, lo);
            *(uint32_t*)(dh + i0 + 8 * DK) = hi;
            *(uint32_t*)(dl + i0 + 8 * DK) = lo;
        }
    }
}

__global__ __launch_bounds__(256) void out_mma_kernel(
    const float* __restrict__ bias, float* __restrict__ out)
{
    const int m0 = blockIdx.y * 128, n0 = blockIdx.x * 128;
    float d[2][8][4];
    gemm_tile_core(g_Oh, g_Ol, g_Wh[3], g_Wl[3], m0, n0, d);

    const int lane = threadIdx.x & 31, wid = threadIdx.x >> 5;
    const int wm = wid >> 1, wn = wid & 1;
#pragma unroll
    for (int mt = 0; mt < 2; mt++) {
        const int r0 = m0 + wm * 32 + mt * 16 + (lane >> 2);
#pragma unroll
        for (int nt = 0; nt < 8; nt++) {
            const int e = n0 + wn * 64 + nt * 8 + (lane & 3) * 2;
            const float b0 = bias[e], b1 = bias[e + 1];
            float* p0 = out + (size_t)r0 * DMODEL + e;
            *(float2*)p0                 = make_float2(d[mt][nt][0] + b0, d[mt][nt][1] + b1);
            *(float2*)(p0 + 8 * DMODEL)  = make_float2(d[mt][nt][2] + b0, d[mt][nt][3] + b1);
        }
    }
}

// ===========================================================================
// Tensor-core causal flash attention, split-bf16, double-buffered K/V.
// 2 smem stages; 1 barrier/tile; per-warp skip of fully-masked tiles;
// base-2 softmax (scale folded with log2e).
// ===========================================================================
#define ASA 72
#define STG (256 * ASA)   // bf16 elems per stage (Kh,Kl,Vh,Vl x 64 rows)

__global__ __launch_bounds__(256) void attn_mma_kernel()
{
    extern __shared__ __nv_bfloat16 sm[];   // 2 * STG elems = 73,728 B

    const int tid  = threadIdx.x;
    const int lane = tid & 31;
    const int w    = tid >> 5;
    const int bh   = blockIdx.y;
    const int b    = bh >> 4, h = bh & 15;
    const int qt   = (int)gridDim.x - 1 - (int)blockIdx.x;   // heavy first
    const int q0   = qt * 128;

    const __nv_bfloat16* Qh = g_qh + (size_t)bh * SEQ * DK;
    const __nv_bfloat16* Ql = g_ql + (size_t)bh * SEQ * DK;
    const __nv_bfloat16* Kh = g_kh + (size_t)bh * SEQ * DK;
    const __nv_bfloat16* Kl = g_kl + (size_t)bh * SEQ * DK;
    const __nv_bfloat16* Vh = g_vh + (size_t)bh * SEQ * DK;
    const __nv_bfloat16* Vl = g_vl + (size_t)bh * SEQ * DK;

    const uint32_t sb = smem_u32(sm);
    const int sub = lane >> 3, l7 = lane & 7;

    // ---- prologue: Q staged in stage-1 area, fragments to registers -------
    uint32_t qfh[4][4], qfl[4][4];
    {
#pragma unroll
        for (int v = 0; v < 4; v++) {
            const int item = v * 256 + tid;
            const int row = item >> 3, sec = item & 7;
            const size_t gi = (size_t)(q0 + row) * DK + sec * 8;
            *(uint4*)(sm + STG + row * ASA + sec * 8)             = *(const uint4*)(Qh + gi);
            *(uint4*)(sm + STG + 128 * ASA + row * ASA + sec * 8) = *(const uint4*)(Ql + gi);
        }
        __syncthreads();
        const int arow = w * 16 + l7 + (sub & 1) * 8;
        const int akof = (sub >> 1) * 8;
#pragma unroll
        for (int ks = 0; ks < 4; ks++) {
            const uint32_t off = (uint32_t)(STG + arow * ASA + ks * 16 + akof) * 2;
            ldsm_x4(qfh[ks][0], qfh[ks][1], qfh[ks][2], qfh[ks][3], sb + off);
            ldsm_x4(qfl[ks][0], qfl[ks][1], qfl[ks][2], qfl[ks][3], sb + (uint32_t)(128 * ASA) * 2 + off);
        }
    }

    float o[8][4];
#pragma unroll
    for (int nt = 0; nt < 8; nt++)
#pragma unroll
        for (int c = 0; c < 4; c++) o[nt][c] = 0.0f;
    float m0r = -1e30f, m1r = -1e30f, l0r = 0.0f, l1r = 0.0f;

    const int g     = lane >> 2;
    const int r0    = q0 + w * 16 + g;
    const int cpair = (lane & 3) * 2;
    const int rmax  = q0 + w * 16 + 15;     // last row this warp owns

    const int ntiles = qt * 2 + 2;
    const int grow = tid >> 3, gsec = tid & 7;   // K/V staging indices (2 items/thr)

    // tile 0 direct to stage 0
#pragma unroll
    for (int v = 0; v < 2; v++) {
        const int row = v * 32 + grow, sec = gsec;
        const size_t gi = (size_t)row * DK + sec * 8;
        const int so = row * ASA + sec * 8;
        *(uint4*)(sm + so)             = *(const uint4*)(Kh + gi);
        *(uint4*)(sm + 64 * ASA + so)  = *(const uint4*)(Kl + gi);
        *(uint4*)(sm + 128 * ASA + so) = *(const uint4*)(Vh + gi);
        *(uint4*)(sm + 192 * ASA + so) = *(const uint4*)(Vl + gi);
    }
    // prefetch tile 1
    uint4 va[2][4];
    if (ntiles > 1) {
#pragma unroll
        for (int v = 0; v < 2; v++) {
            const int row = v * 32 + grow;
            const size_t gi = (size_t)(64 + row) * DK + gsec * 8;
            va[v][0] = *(const uint4*)(Kh + gi);
            va[v][1] = *(const uint4*)(Kl + gi);
            va[v][2] = *(const uint4*)(Vh + gi);
            va[v][3] = *(const uint4*)(Vl + gi);
        }
    }
    __syncthreads();   // Q-frag reads done (program order); tile 0 visible

    const float sc2 = 0.18033688011f;   // 0.125 * log2(e)

    for (int kt = 0; kt < ntiles; kt++) {
        const int k0 = kt * 64;
        const uint32_t cb = sb + (uint32_t)((kt & 1) * STG) * 2;  // current stage base (bytes)

        // store prefetched tile kt+1 into the other stage; prefetch kt+2
        if (kt + 1 < ntiles) {
            __nv_bfloat16* nx = sm + ((kt + 1) & 1) * STG;
#pragma unroll
            for (int v = 0; v < 2; v++) {
                const int row = v * 32 + grow;
                const int so = row * ASA + gsec * 8;
                *(uint4*)(nx + so)             = va[v][0];
                *(uint4*)(nx + 64 * ASA + so)  = va[v][1];
                *(uint4*)(nx + 128 * ASA + so) = va[v][2];
                *(uint4*)(nx + 192 * ASA + so) = va[v][3];
            }
            if (kt + 2 < ntiles) {
                const int nk0 = k0 + 128;
#pragma unroll
                for (int v = 0; v < 2; v++) {
                    const int row = v * 32 + grow;
                    const size_t gi = (size_t)(nk0 + row) * DK + gsec * 8;
                    va[v][0] = *(const uint4*)(Kh + gi);
                    va[v][1] = *(const uint4*)(Kl + gi);
                    va[v][2] = *(const uint4*)(Vh + gi);
                    va[v][3] = *(const uint4*)(Vl + gi);
                }
            }
        }

        if (k0 <= rmax) {   // warp has at least one unmasked key in this tile
            // ---- S = Q K^T -----------------------------------------------
            float d[8][4];
#pragma unroll
            for (int nt = 0; nt < 8; nt++)
#pragma unroll
                for (int c = 0; c < 4; c++) d[nt][c] = 0.0f;

            const int brow = l7 + (sub >> 1) * 8;
            const int bkof = (sub & 1) * 8;
#pragma unroll
            for (int ks = 0; ks < 4; ks++) {
                uint32_t fh[8][2], fl[8][2];
#pragma unroll
                for (int g2 = 0; g2 < 4; g2++) {
                    const uint32_t off = (uint32_t)((g2 * 16 + brow) * ASA + ks * 16 + bkof) * 2;
                    ldsm_x4(fh[2 * g2][0], fh[2 * g2][1], fh[2 * g2 + 1][0], fh[2 * g2 + 1][1], cb + off);
                    ldsm_x4(fl[2 * g2][0], fl[2 * g2][1], fl[2 * g2 + 1][0], fl[2 * g2 + 1][1], cb + (uint32_t)(64 * ASA) * 2 + off);
                }
#pragma unroll
                for (int nt = 0; nt < 8; nt++) {
                    mma16816(d[nt], qfh[ks], fh[nt]);
                    mma16816(d[nt], qfh[ks], fl[nt]);
                    mma16816(d[nt], qfl[ks], fh[nt]);
                }
            }

            // ---- scale (base-2) + causal mask ----------------------------
            const bool need_mask = (k0 + 63 > q0 + w * 16);
#pragma unroll
            for (int nt = 0; nt < 8; nt++) {
                const int key0 = k0 + nt * 8 + cpair;
                float v0 = d[nt][0] * sc2, v1 = d[nt][1] * sc2;
                float v2 = d[nt][2] * sc2, v3 = d[nt][3] * sc2;
                if (need_mask) {
                    if (key0     > r0)     v0 = -1e30f;
                    if (key0 + 1 > r0)     v1 = -1e30f;
                    if (key0     > r0 + 8) v2 = -1e30f;
                    if (key0 + 1 > r0 + 8) v3 = -1e30f;
                }
                d[nt][0] = v0; d[nt][1] = v1; d[nt][2] = v2; d[nt][3] = v3;
            }

            // ---- online softmax (rows r0, r0+8), base-2 ------------------
            float mx0 = -1e30f, mx1 = -1e30f;
#pragma unroll
            for (int nt = 0; nt < 8; nt++) {
                mx0 = fmaxf(mx0, fmaxf(d[nt][0], d[nt][1]));
                mx1 = fmaxf(mx1, fmaxf(d[nt][2], d[nt][3]));
            }
            mx0 = fmaxf(mx0, __shfl_xor_sync(0xffffffffu, mx0, 1));
            mx0 = fmaxf(mx0, __shfl_xor_sync(0xffffffffu, mx0, 2));
            mx1 = fmaxf(mx1, __shfl_xor_sync(0xffffffffu, mx1, 1));
            mx1 = fmaxf(mx1, __shfl_xor_sync(0xffffffffu, mx1, 2));

            const float mn0 = fmaxf(m0r, mx0);
            const float mn1 = fmaxf(m1r, mx1);
            const float a0 = ex2f(m0r - mn0);
            const float a1 = ex2f(m1r - mn1);
            m0r = mn0; m1r = mn1;

            float rs0 = 0.0f, rs1 = 0.0f;
#pragma unroll
            for (int nt = 0; nt < 8; nt++) {
                d[nt][0] = ex2f(d[nt][0] - mn0);
                d[nt][1] = ex2f(d[nt][1] - mn0);
                d[nt][2] = ex2f(d[nt][2] - mn1);
                d[nt][3] = ex2f(d[nt][3] - mn1);
                rs0 += d[nt][0] + d[nt][1];
                rs1 += d[nt][2] + d[nt][3];
            }
            rs0 += __shfl_xor_sync(0xffffffffu, rs0, 1);
            rs0 += __shfl_xor_sync(0xffffffffu, rs0, 2);
            rs1 += __shfl_xor_sync(0xffffffffu, rs1, 1);
            rs1 += __shfl_xor_sync(0xffffffffu, rs1, 2);
            l0r = l0r * a0 + rs0;
            l1r = l1r * a1 + rs1;

#pragma unroll
            for (int nt = 0; nt < 8; nt++) {
                o[nt][0] *= a0; o[nt][1] *= a0;
                o[nt][2] *= a1; o[nt][3] *= a1;
            }

            // ---- O += P V -------------------------------------------------
#pragma unroll
            for (int kst = 0; kst < 4; kst++) {
                uint32_t pah[4], pal[4];
                split2(d[2 * kst][0],     d[2 * kst][1],     pah[0], pal[0]);
                split2(d[2 * kst][2],     d[2 * kst][3],     pah[1], pal[1]);
                split2(d[2 * kst + 1][0], d[2 * kst + 1][1], pah[2], pal[2]);
                split2(d[2 * kst + 1][2], d[2 * kst + 1][3], pah[3], pal[3]);
                const int vrow = kst * 16 + l7 + (sub & 1) * 8;
                const int vkof = (sub >> 1) * 8;
#pragma unroll
                for (int g2 = 0; g2 < 4; g2++) {
                    uint32_t vh[4], vl[4];
                    const uint32_t off = (uint32_t)(vrow * ASA + g2 * 16 + vkof) * 2;
                    ldsm_x4t(vh[0], vh[1], vh[2], vh[3], cb + (uint32_t)(128 * ASA) * 2 + off);
                    ldsm_x4t(vl[0], vl[1], vl[2], vl[3], cb + (uint32_t)(192 * ASA) * 2 + off);
                    mma16816(o[2 * g2],     pah, &vh[0]);
                    mma16816(o[2 * g2],     pah, &vl[0]);
                    mma16816(o[2 * g2],     pal, &vh[0]);
                    mma16816(o[2 * g2 + 1], pah, &vh[2]);
                    mma16816(o[2 * g2 + 1], pah, &vl[2]);
                    mma16816(o[2 * g2 + 1], pal, &vh[2]);
                }
            }
        }
        __syncthreads();
    }

    // ---- epilogue: normalize, split to bf16 hi/lo in [b,s,h*dk] -----------
    const float i0 = 1.0f / l0r;
    const float i1 = 1.0f / l1r;
#pragma unroll
    for (int nt = 0; nt < 8; nt++) {
        const int dkc = h * 64 + nt * 8 + cpair;
        const size_t idx = ((size_t)b * SEQ + r0) * DMODEL + dkc;
        uint32_t hi, lo;
        split2(o[nt][0] * i0, o[nt][1] * i0, hi, lo);
        *(uint32_t*)(g_Oh + idx) = hi;
        *(uint32_t*)(g_Ol + idx) = lo;
        split2(o[nt][2] * i1, o[nt][3] * i1, hi, lo);
        *(uint32_t*)(g_Oh + idx + 8 * DMODEL) = hi;
        *(uint32_t*)(g_Ol + idx + 8 * DMODEL) = lo;
    }
}

// ===========================================================================
extern "C" void kernel_launch(void* const* d_in, const int* in_sizes, int n_in,
                              void* d_out, int out_size)
{
    (void)in_sizes; (void)n_in; (void)out_size;
    const float* x  = (const float*)d_in[0];
    const float* Wq = (const float*)d_in[1];
    const float* Wk = (const float*)d_in[2];
    const float* Wv = (const float*)d_in[3];
    const float* Wo = (const float*)d_in[4];
    const float* bo = (const float*)d_in[5];
    float* out = (float*)d_out;

    const int ATTN_SMEM = 2 * STG * (int)sizeof(__nv_bfloat16);   // 73,728 B
    cudaFuncSetAttribute(attn_mma_kernel,
                         cudaFuncAttributeMaxDynamicSharedMemorySize, ATTN_SMEM);

    const int nX4 = MROWS * DMODEL / 4;
    const int nW4 = DMODEL * DMODEL / 4;
    cvt_split_kernel<<<nX4 / 256, 256>>>(x,  0, nX4);
    cvt_split_kernel<<<nW4 / 256, 256>>>(Wq, 1, nW4);
    cvt_split_kernel<<<nW4 / 256, 256>>>(Wk, 2, nW4);
    cvt_split_kernel<<<nW4 / 256, 256>>>(Wv, 3, nW4);
    cvt_split_kernel<<<nW4 / 256, 256>>>(Wo, 4, nW4);

    qkv_mma_kernel<<<dim3(DMODEL / 128, MROWS / 128, 3), 256>>>();
    attn_mma_kernel<<<dim3(SEQ / 128, BATCH * NHEADS), 256, ATTN_SMEM>>>();
    out_mma_kernel<<<dim3(DMODEL / 128, MROWS / 128), 256>>>(bo, out);
}

// round 11
// speedup vs baseline: 2.8468x; 1.1454x over previous
#include <cuda_runtime.h>
#include <cuda_bf16.h>
#include <math.h>
#include <stdint.h>

#define BATCH   2
#define SEQ     2048
#define DMODEL  1024
#define NHEADS  16
#define DK      64
#define MROWS   (BATCH * SEQ)   // 4096

// -------------------- scratch (__device__ globals; no allocations) ---------
__device__ __nv_bfloat16 g_Xh[(size_t)MROWS * DMODEL];
__device__ __nv_bfloat16 g_Xl[(size_t)MROWS * DMODEL];
__device__ __nv_bfloat16 g_Wh[4][(size_t)DMODEL * DMODEL];  // q,k,v,o
__device__ __nv_bfloat16 g_Wl[4][(size_t)DMODEL * DMODEL];
__device__ __nv_bfloat16 g_qh[(size_t)BATCH * NHEADS * SEQ * DK];
__device__ __nv_bfloat16 g_ql[(size_t)BATCH * NHEADS * SEQ * DK];
__device__ __nv_bfloat16 g_kh[(size_t)BATCH * NHEADS * SEQ * DK];
__device__ __nv_bfloat16 g_kl[(size_t)BATCH * NHEADS * SEQ * DK];
__device__ __nv_bfloat16 g_vh[(size_t)BATCH * NHEADS * SEQ * DK];
__device__ __nv_bfloat16 g_vl[(size_t)BATCH * NHEADS * SEQ * DK];
__device__ __nv_bfloat16 g_Oh[(size_t)MROWS * DMODEL];
__device__ __nv_bfloat16 g_Ol[(size_t)MROWS * DMODEL];

// readiness counters (zeroed by cvt_all_kernel every call)
__device__ int g_cntPair[8];   // qkv CTAs done per head-pair (target 96)
__device__ int g_cntO[32];     // attn CTAs done per (b,qt) m-block (target 16)

// ===========================================================================
// warp-MMA helpers (arch-portable sm_80+ ISA)
// ===========================================================================
__device__ __forceinline__ uint32_t smem_u32(const void* p) {
    uint32_t a;
    asm("{ .reg .u64 t; cvta.to.shared.u64 t, %1; cvt.u32.u64 %0, t; }"
        : "=r"(a) : "l"(p));
    return a;
}

__device__ __forceinline__ void ldsm_x4(uint32_t& r0, uint32_t& r1,
                                        uint32_t& r2, uint32_t& r3, uint32_t addr) {
    asm volatile("ldmatrix.sync.aligned.m8n8.x4.shared.b16 {%0,%1,%2,%3}, [%4];"
                 : "=r"(r0), "=r"(r1), "=r"(r2), "=r"(r3) : "r"(addr));
}

__device__ __forceinline__ void ldsm_x4t(uint32_t& r0, uint32_t& r1,
                                         uint32_t& r2, uint32_t& r3, uint32_t addr) {
    asm volatile("ldmatrix.sync.aligned.m8n8.x4.trans.shared.b16 {%0,%1,%2,%3}, [%4];"
                 : "=r"(r0), "=r"(r1), "=r"(r2), "=r"(r3) : "r"(addr));
}

__device__ __forceinline__ void mma16816(float* d, const uint32_t* a, const uint32_t* b) {
    asm volatile(
        "mma.sync.aligned.m16n8k16.row.col.f32.bf16.bf16.f32 "
        "{%0,%1,%2,%3}, {%4,%5,%6,%7}, {%8,%9}, {%0,%1,%2,%3};"
        : "+f"(d[0]), "+f"(d[1]), "+f"(d[2]), "+f"(d[3])
        : "r"(a[0]), "r"(a[1]), "r"(a[2]), "r"(a[3]), "r"(b[0]), "r"(b[1]));
}

__device__ __forceinline__ float ex2f(float x) {
    float r;
    asm("ex2.approx.f32 %0, %1;" : "=f"(r) : "f"(x));
    return r;
}

__device__ __forceinline__ void split2(float x, float y, uint32_t& hi, uint32_t& lo) {
    uint32_t h;
    asm("cvt.rn.bf16x2.f32 %0, %1, %2;" : "=r"(h) : "f"(y), "f"(x));
    const float hx = __uint_as_float(h << 16);
    const float hy = __uint_as_float(h & 0xFFFF0000u);
    const float rx = x - hx, ry = y - hy;
    uint32_t l;
    asm("cvt.rn.bf16x2.f32 %0, %1, %2;" : "=r"(l) : "f"(ry), "f"(rx));
    hi = h; lo = l;
}

__device__ __forceinline__ int ld_acq(const int* p) {
    int v;
    asm volatile("ld.acquire.gpu.b32 %0, [%1];" : "=r"(v) : "l"(p) : "memory");
    return v;
}

// ===========================================================================
// merged fp32 -> (hi, lo) split for X + 4 W's; also zeroes sync counters
// ===========================================================================
#define NX4 (MROWS * DMODEL / 4)     // 1,048,576
#define NW4 (DMODEL * DMODEL / 4)    //   262,144

__global__ void cvt_all_kernel(const float* __restrict__ x,
                               const float* __restrict__ wq,
                               const float* __restrict__ wk,
                               const float* __restrict__ wv,
                               const float* __restrict__ wo)
{
    if (blockIdx.x == 0 && threadIdx.x < 40) {
        if (threadIdx.x < 8) g_cntPair[threadIdx.x] = 0;
        else                 g_cntO[threadIdx.x - 8] = 0;
    }
    const int i = blockIdx.x * blockDim.x + threadIdx.x;
    const float* src;
    __nv_bfloat16 *hi, *lo;
    int idx;
    if (i < NX4) { src = x; hi = g_Xh; lo = g_Xl; idx = i; }
    else {
        const int j = i - NX4;
        const int wsel = j / NW4;
        idx = j - wsel * NW4;
        src = (wsel == 0) ? wq : (wsel == 1) ? wk : (wsel == 2) ? wv : wo;
        hi = g_Wh[wsel]; lo = g_Wl[wsel];
    }
    float4 v = ((const float4*)src)[idx];
    uint32_t h0, h1, l0, l1;
    split2(v.x, v.y, h0, l0);
    split2(v.z, v.w, h1, l1);
    ((uint2*)hi)[idx] = make_uint2(h0, h1);
    ((uint2*)lo)[idx] = make_uint2(l0, l1);
}

// ===========================================================================
// Split-bf16 GEMM core (logic unchanged from R9/R10 — at the HMMA ceiling).
// Now parameterized on a dynamic-smem buffer (needs 40,960 B).
// ===========================================================================
#define SA 40

__device__ __forceinline__ void gemm_tile_core(
    const __nv_bfloat16* __restrict__ Ah, const __nv_bfloat16* __restrict__ Al,
    const __nv_bfloat16* __restrict__ Bh, const __nv_bfloat16* __restrict__ Bl,
    int m0, int n0, float d[2][8][4], char* sbuf)
{
    __nv_bfloat16* sAh = (__nv_bfloat16*)sbuf;
    __nv_bfloat16* sAl = sAh + 128 * SA;
    __nv_bfloat16* sBh = sAl + 128 * SA;
    __nv_bfloat16* sBl = sBh + 128 * SA;

    const int tid  = threadIdx.x;
    const int lane = tid & 31;
    const int wid  = tid >> 5;
    const int wm   = wid >> 1;
    const int wn   = wid & 1;

    const uint32_t aAh = smem_u32(sAh), aAl = smem_u32(sAl);
    const uint32_t aBh = smem_u32(sBh), aBl = smem_u32(sBl);

    const int sub  = lane >> 3, l7 = lane & 7;
    const int arow = wm * 32 + l7 + (sub & 1) * 8;
    const int akof = (sub >> 1) * 8;
    const int brow = wn * 64 + l7 + (sub >> 1) * 8;
    const int bkof = (sub & 1) * 8;

    const int grow = tid >> 2;
    const int gq   = (tid & 3) * 8;

#pragma unroll
    for (int mt = 0; mt < 2; mt++)
#pragma unroll
        for (int nt = 0; nt < 8; nt++)
#pragma unroll
            for (int c = 0; c < 4; c++) d[mt][nt][c] = 0.0f;

    uint4 va[2][4];
#pragma unroll
    for (int p = 0; p < 2; p++) {
        const size_t ga = (size_t)(m0 + p * 64 + grow) * DMODEL + gq;
        const size_t gb = (size_t)(n0 + p * 64 + grow) * DMODEL + gq;
        va[p][0] = *(const uint4*)(Ah + ga);
        va[p][1] = *(const uint4*)(Al + ga);
        va[p][2] = *(const uint4*)(Bh + gb);
        va[p][3] = *(const uint4*)(Bl + gb);
    }

    for (int it = 0; it < DMODEL / 32; it++) {
        __syncthreads();
#pragma unroll
        for (int p = 0; p < 2; p++) {
            const int so = (p * 64 + grow) * SA + gq;
            *(uint4*)(sAh + so) = va[p][0];
            *(uint4*)(sAl + so) = va[p][1];
            *(uint4*)(sBh + so) = va[p][2];
            *(uint4*)(sBl + so) = va[p][3];
        }
        if (it + 1 < DMODEL / 32) {
            const int k0 = (it + 1) * 32;
#pragma unroll
            for (int p = 0; p < 2; p++) {
                const size_t ga = (size_t)(m0 + p * 64 + grow) * DMODEL + k0 + gq;
                const size_t gb = (size_t)(n0 + p * 64 + grow) * DMODEL + k0 + gq;
                va[p][0] = *(const uint4*)(Ah + ga);
                va[p][1] = *(const uint4*)(Al + ga);
                va[p][2] = *(const uint4*)(Bh + gb);
                va[p][3] = *(const uint4*)(Bl + gb);
            }
        }
        __syncthreads();

#pragma unroll
        for (int s = 0; s < 2; s++) {
            const int ks = s * 16;
            uint32_t fAh[2][4], fAl[2][4], fBh[8][2], fBl[8][2];
#pragma unroll
            for (int mt = 0; mt < 2; mt++) {
                const uint32_t off = ((arow + mt * 16) * SA + ks + akof) * 2;
                ldsm_x4(fAh[mt][0], fAh[mt][1], fAh[mt][2], fAh[mt][3], aAh + off);
                ldsm_x4(fAl[mt][0], fAl[mt][1], fAl[mt][2], fAl[mt][3], aAl + off);
            }
#pragma unroll
            for (int g = 0; g < 4; g++) {
                const uint32_t off = ((brow + g * 16) * SA + ks + bkof) * 2;
                ldsm_x4(fBh[2 * g][0], fBh[2 * g][1], fBh[2 * g + 1][0], fBh[2 * g + 1][1], aBh + off);
                ldsm_x4(fBl[2 * g][0], fBl[2 * g][1], fBl[2 * g + 1][0], fBl[2 * g + 1][1], aBl + off);
            }
#pragma unroll
            for (int mt = 0; mt < 2; mt++)
#pragma unroll
                for (int nt = 0; nt < 8; nt++) {
                    mma16816(d[mt][nt], fAh[mt], fBh[nt]);
                    mma16816(d[mt][nt], fAh[mt], fBl[nt]);
                    mma16816(d[mt][nt], fAl[mt], fBh[nt]);
                }
        }
    }
}

// ---------------- qkv role body -------------------------------------------
__device__ __forceinline__ void qkv_work(char* sbuf, int z, int m0, int n0)
{
    float d[2][8][4];
    gemm_tile_core(g_Xh, g_Xl, g_Wh[z], g_Wl[z], m0, n0, d, sbuf);

    __nv_bfloat16* dh = (z == 0) ? g_qh : (z == 1 ? g_kh : g_vh);
    __nv_bfloat16* dl = (z == 0) ? g_ql : (z == 1 ? g_kl : g_vl);
    const int lane = threadIdx.x & 31, wid = threadIdx.x >> 5;
    const int wm = wid >> 1, wn = wid & 1;
#pragma unroll
    for (int mt = 0; mt < 2; mt++) {
        const int r0 = m0 + wm * 32 + mt * 16 + (lane >> 2);
        const int b = r0 >> 11;
        const int s = r0 & (SEQ - 1);
#pragma unroll
        for (int nt = 0; nt < 8; nt++) {
            const int e  = n0 + wn * 64 + nt * 8 + (lane & 3) * 2;
            const int h  = e >> 6, dk = e & 63;
            const size_t i0 = (((size_t)b * NHEADS + h) * SEQ + s) * DK + dk;
            uint32_t hi, lo;
            split2(d[mt][nt][0], d[mt][nt][1], hi, lo);
            *(uint32_t*)(dh + i0) = hi;
            *(uint32_t*)(dl + i0) = lo;
            split2(d[mt][nt][2], d[mt][nt][3], hi, lo);
            *(uint32_t*)(dh + i0 + 8 * DK) = hi;
            *(uint32_t*)(dl + i0 + 8 * DK) = lo;
        }
    }
}

// ---------------- out-proj role body --------------------------------------
__device__ __forceinline__ void out_work(char* sbuf, int m0, int n0,
                                         const float* __restrict__ bias,
                                         float* __restrict__ out)
{
    float d[2][8][4];
    gemm_tile_core(g_Oh, g_Ol, g_Wh[3], g_Wl[3], m0, n0, d, sbuf);

    const int lane = threadIdx.x & 31, wid = threadIdx.x >> 5;
    const int wm = wid >> 1, wn = wid & 1;
#pragma unroll
    for (int mt = 0; mt < 2; mt++) {
        const int r0 = m0 + wm * 32 + mt * 16 + (lane >> 2);
#pragma unroll
        for (int nt = 0; nt < 8; nt++) {
            const int e = n0 + wn * 64 + nt * 8 + (lane & 3) * 2;
            const float b0 = bias[e], b1 = bias[e + 1];
            float* p0 = out + (size_t)r0 * DMODEL + e;
            *(float2*)p0                 = make_float2(d[mt][nt][0] + b0, d[mt][nt][1] + b1);
            *(float2*)(p0 + 8 * DMODEL)  = make_float2(d[mt][nt][2] + b0, d[mt][nt][3] + b1);
        }
    }
}

// ---------------- attention role body (logic unchanged from R10) ----------
#define ASA 72
#define STG (256 * ASA)

__device__ __forceinline__ void attn_work(char* sbuf, int b, int h, int qt)
{
    __nv_bfloat16* sm = (__nv_bfloat16*)sbuf;   // 2 * STG elems = 73,728 B

    const int tid  = threadIdx.x;
    const int lane = tid & 31;
    const int w    = tid >> 5;
    const int bh   = b * NHEADS + h;
    const int q0   = qt * 128;

    const __nv_bfloat16* Qh = g_qh + (size_t)bh * SEQ * DK;
    const __nv_bfloat16* Ql = g_ql + (size_t)bh * SEQ * DK;
    const __nv_bfloat16* Kh = g_kh + (size_t)bh * SEQ * DK;
    const __nv_bfloat16* Kl = g_kl + (size_t)bh * SEQ * DK;
    const __nv_bfloat16* Vh = g_vh + (size_t)bh * SEQ * DK;
    const __nv_bfloat16* Vl = g_vl + (size_t)bh * SEQ * DK;

    const uint32_t sb = smem_u32(sm);
    const int sub = lane >> 3, l7 = lane & 7;

    // ---- prologue: Q staged in stage-1 area, fragments to registers -------
    uint32_t qfh[4][4], qfl[4][4];
    {
#pragma unroll
        for (int v = 0; v < 4; v++) {
            const int item = v * 256 + tid;
            const int row = item >> 3, sec = item & 7;
            const size_t gi = (size_t)(q0 + row) * DK + sec * 8;
            *(uint4*)(sm + STG + row * ASA + sec * 8)             = *(const uint4*)(Qh + gi);
            *(uint4*)(sm + STG + 128 * ASA + row * ASA + sec * 8) = *(const uint4*)(Ql + gi);
        }
        __syncthreads();
        const int arow = w * 16 + l7 + (sub & 1) * 8;
        const int akof = (sub >> 1) * 8;
#pragma unroll
        for (int ks = 0; ks < 4; ks++) {
            const uint32_t off = (uint32_t)(STG + arow * ASA + ks * 16 + akof) * 2;
            ldsm_x4(qfh[ks][0], qfh[ks][1], qfh[ks][2], qfh[ks][3], sb + off);
            ldsm_x4(qfl[ks][0], qfl[ks][1], qfl[ks][2], qfl[ks][3], sb + (uint32_t)(128 * ASA) * 2 + off);
        }
    }

    float o[8][4];
#pragma unroll
    for (int nt = 0; nt < 8; nt++)
#pragma unroll
        for (int c = 0; c < 4; c++) o[nt][c] = 0.0f;
    float m0r = -1e30f, m1r = -1e30f, l0r = 0.0f, l1r = 0.0f;

    const int g     = lane >> 2;
    const int r0    = q0 + w * 16 + g;
    const int cpair = (lane & 3) * 2;
    const int rmax  = q0 + w * 16 + 15;

    const int ntiles = qt * 2 + 2;
    const int grow = tid >> 3, gsec = tid & 7;

    // tile 0 direct to stage 0
#pragma unroll
    for (int v = 0; v < 2; v++) {
        const int row = v * 32 + grow, sec = gsec;
        const size_t gi = (size_t)row * DK + sec * 8;
        const int so = row * ASA + sec * 8;
        *(uint4*)(sm + so)             = *(const uint4*)(Kh + gi);
        *(uint4*)(sm + 64 * ASA + so)  = *(const uint4*)(Kl + gi);
        *(uint4*)(sm + 128 * ASA + so) = *(const uint4*)(Vh + gi);
        *(uint4*)(sm + 192 * ASA + so) = *(const uint4*)(Vl + gi);
    }
    // prefetch tile 1
    uint4 va[2][4];
    if (ntiles > 1) {
#pragma unroll
        for (int v = 0; v < 2; v++) {
            const int row = v * 32 + grow;
            const size_t gi = (size_t)(64 + row) * DK + gsec * 8;
            va[v][0] = *(const uint4*)(Kh + gi);
            va[v][1] = *(const uint4*)(Kl + gi);
            va[v][2] = *(const uint4*)(Vh + gi);
            va[v][3] = *(const uint4*)(Vl + gi);
        }
    }
    __syncthreads();

    const float sc2 = 0.18033688011f;   // 0.125 * log2(e)

    for (int kt = 0; kt < ntiles; kt++) {
        const int k0 = kt * 64;
        const uint32_t cb = sb + (uint32_t)((kt & 1) * STG) * 2;

        if (kt + 1 < ntiles) {
            __nv_bfloat16* nx = sm + ((kt + 1) & 1) * STG;
#pragma unroll
            for (int v = 0; v < 2; v++) {
                const int row = v * 32 + grow;
                const int so = row * ASA + gsec * 8;
                *(uint4*)(nx + so)             = va[v][0];
                *(uint4*)(nx + 64 * ASA + so)  = va[v][1];
                *(uint4*)(nx + 128 * ASA + so) = va[v][2];
                *(uint4*)(nx + 192 * ASA + so) = va[v][3];
            }
            if (kt + 2 < ntiles) {
                const int nk0 = k0 + 128;
#pragma unroll
                for (int v = 0; v < 2; v++) {
                    const int row = v * 32 + grow;
                    const size_t gi = (size_t)(nk0 + row) * DK + gsec * 8;
                    va[v][0] = *(const uint4*)(Kh + gi);
                    va[v][1] = *(const uint4*)(Kl + gi);
                    va[v][2] = *(const uint4*)(Vh + gi);
                    va[v][3] = *(const uint4*)(Vl + gi);
                }
            }
        }

        if (k0 <= rmax) {
            // ---- S = Q K^T -----------------------------------------------
            float d[8][4];
#pragma unroll
            for (int nt = 0; nt < 8; nt++)
#pragma unroll
                for (int c = 0; c < 4; c++) d[nt][c] = 0.0f;

            const int brow = l7 + (sub >> 1) * 8;
            const int bkof = (sub & 1) * 8;
#pragma unroll
            for (int ks = 0; ks < 4; ks++) {
                uint32_t fh[8][2], fl[8][2];
#pragma unroll
                for (int g2 = 0; g2 < 4; g2++) {
                    const uint32_t off = (uint32_t)((g2 * 16 + brow) * ASA + ks * 16 + bkof) * 2;
                    ldsm_x4(fh[2 * g2][0], fh[2 * g2][1], fh[2 * g2 + 1][0], fh[2 * g2 + 1][1], cb + off);
                    ldsm_x4(fl[2 * g2][0], fl[2 * g2][1], fl[2 * g2 + 1][0], fl[2 * g2 + 1][1], cb + (uint32_t)(64 * ASA) * 2 + off);
                }
#pragma unroll
                for (int nt = 0; nt < 8; nt++) {
                    mma16816(d[nt], qfh[ks], fh[nt]);
                    mma16816(d[nt], qfh[ks], fl[nt]);
                    mma16816(d[nt], qfl[ks], fh[nt]);
                }
            }

            // ---- scale (base-2) + causal mask ----------------------------
            const bool need_mask = (k0 + 63 > q0 + w * 16);
#pragma unroll
            for (int nt = 0; nt < 8; nt++) {
                const int key0 = k0 + nt * 8 + cpair;
                float v0 = d[nt][0] * sc2, v1 = d[nt][1] * sc2;
                float v2 = d[nt][2] * sc2, v3 = d[nt][3] * sc2;
                if (need_mask) {
                    if (key0     > r0)     v0 = -1e30f;
                    if (key0 + 1 > r0)     v1 = -1e30f;
                    if (key0     > r0 + 8) v2 = -1e30f;
                    if (key0 + 1 > r0 + 8) v3 = -1e30f;
                }
                d[nt][0] = v0; d[nt][1] = v1; d[nt][2] = v2; d[nt][3] = v3;
            }

            // ---- online softmax (rows r0, r0+8), base-2 ------------------
            float mx0 = -1e30f, mx1 = -1e30f;
#pragma unroll
            for (int nt = 0; nt < 8; nt++) {
                mx0 = fmaxf(mx0, fmaxf(d[nt][0], d[nt][1]));
                mx1 = fmaxf(mx1, fmaxf(d[nt][2], d[nt][3]));
            }
            mx0 = fmaxf(mx0, __shfl_xor_sync(0xffffffffu, mx0, 1));
            mx0 = fmaxf(mx0, __shfl_xor_sync(0xffffffffu, mx0, 2));
            mx1 = fmaxf(mx1, __shfl_xor_sync(0xffffffffu, mx1, 1));
            mx1 = fmaxf(mx1, __shfl_xor_sync(0xffffffffu, mx1, 2));

            const float mn0 = fmaxf(m0r, mx0);
            const float mn1 = fmaxf(m1r, mx1);
            const float a0 = ex2f(m0r - mn0);
            const float a1 = ex2f(m1r - mn1);
            m0r = mn0; m1r = mn1;

            float rs0 = 0.0f, rs1 = 0.0f;
#pragma unroll
            for (int nt = 0; nt < 8; nt++) {
                d[nt][0] = ex2f(d[nt][0] - mn0);
                d[nt][1] = ex2f(d[nt][1] - mn0);
                d[nt][2] = ex2f(d[nt][2] - mn1);
                d[nt][3] = ex2f(d[nt][3] - mn1);
                rs0 += d[nt][0] + d[nt][1];
                rs1 += d[nt][2] + d[nt][3];
            }
            rs0 += __shfl_xor_sync(0xffffffffu, rs0, 1);
            rs0 += __shfl_xor_sync(0xffffffffu, rs0, 2);
            rs1 += __shfl_xor_sync(0xffffffffu, rs1, 1);
            rs1 += __shfl_xor_sync(0xffffffffu, rs1, 2);
            l0r = l0r * a0 + rs0;
            l1r = l1r * a1 + rs1;

#pragma unroll
            for (int nt = 0; nt < 8; nt++) {
                o[nt][0] *= a0; o[nt][1] *= a0;
                o[nt][2] *= a1; o[nt][3] *= a1;
            }

            // ---- O += P V -------------------------------------------------
#pragma unroll
            for (int kst = 0; kst < 4; kst++) {
                uint32_t pah[4], pal[4];
                split2(d[2 * kst][0],     d[2 * kst][1],     pah[0], pal[0]);
                split2(d[2 * kst][2],     d[2 * kst][3],     pah[1], pal[1]);
                split2(d[2 * kst + 1][0], d[2 * kst + 1][1], pah[2], pal[2]);
                split2(d[2 * kst + 1][2], d[2 * kst + 1][3], pah[3], pal[3]);
                const int vrow = kst * 16 + l7 + (sub & 1) * 8;
                const int vkof = (sub >> 1) * 8;
#pragma unroll
                for (int g2 = 0; g2 < 4; g2++) {
                    uint32_t vh[4], vl[4];
                    const uint32_t off = (uint32_t)(vrow * ASA + g2 * 16 + vkof) * 2;
                    ldsm_x4t(vh[0], vh[1], vh[2], vh[3], cb + (uint32_t)(128 * ASA) * 2 + off);
                    ldsm_x4t(vl[0], vl[1], vl[2], vl[3], cb + (uint32_t)(192 * ASA) * 2 + off);
                    mma16816(o[2 * g2],     pah, &vh[0]);
                    mma16816(o[2 * g2],     pah, &vl[0]);
                    mma16816(o[2 * g2],     pal, &vh[0]);
                    mma16816(o[2 * g2 + 1], pah, &vh[2]);
                    mma16816(o[2 * g2 + 1], pah, &vl[2]);
                    mma16816(o[2 * g2 + 1], pal, &vh[2]);
                }
            }
        }
        __syncthreads();
    }

    // ---- epilogue: normalize, split to bf16 hi/lo in [b,s,h*dk] -----------
    const float i0 = 1.0f / l0r;
    const float i1 = 1.0f / l1r;
#pragma unroll
    for (int nt = 0; nt < 8; nt++) {
        const int dkc = h * 64 + nt * 8 + cpair;
        const size_t idx = ((size_t)b * SEQ + r0) * DMODEL + dkc;
        uint32_t hi, lo;
        split2(o[nt][0] * i0, o[nt][1] * i0, hi, lo);
        *(uint32_t*)(g_Oh + idx) = hi;
        *(uint32_t*)(g_Ol + idx) = lo;
        split2(o[nt][2] * i1, o[nt][3] * i1, hi, lo);
        *(uint32_t*)(g_Oh + idx + 8 * DMODEL) = hi;
        *(uint32_t*)(g_Ol + idx + 8 * DMODEL) = lo;
    }
}

// ===========================================================================
// Mega-kernel: role by blockIdx. Producers precede consumers in bid order,
// so dependency spins cannot deadlock (dispatch follows bid order).
//   bid [0,768):    qkv   — pair-major: nx = bid/96, then (my, z)
//   bid [768,1280): attn  — pair-major, heavy-qt first within pair
//   bid [1280,1536): out-proj
// ===========================================================================
#define MEGA_SMEM (2 * STG * 2)   // 73,728 B (attn is the max user)

__global__ __launch_bounds__(256) void mega_kernel(
    const float* __restrict__ bias, float* __restrict__ out)
{
    extern __shared__ char sbuf[];
    const int bid = blockIdx.x;
    const int tid = threadIdx.x;

    if (bid < 768) {
        // ---- qkv role ----
        const int nx  = bid / 96;          // head-pair (n-block)
        const int rem = bid - nx * 96;
        const int my  = rem / 3;           // m-block (0..31)
        const int z   = rem - my * 3;      // 0=Q, 1=K, 2=V
        qkv_work(sbuf, z, my * 128, nx * 128);
        __threadfence();
        __syncthreads();
        if (tid == 0) atomicAdd(&g_cntPair[nx], 1);
    } else if (bid < 1280) {
        // ---- attention role ----
        const int abid = bid - 768;
        const int pair = abid >> 6;        // 0..7, matches qkv nx
        const int w64  = abid & 63;
        const int qt   = 15 - (w64 >> 2);  // heavy first within pair
        const int bs   = w64 & 3;
        const int b    = bs >> 1;
        const int h    = pair * 2 + (bs & 1);
        if (tid == 0) { while (ld_acq(&g_cntPair[pair]) < 96) { } }
        __syncthreads();
        attn_work(sbuf, b, h, qt);
        __threadfence();
        __syncthreads();
        if (tid == 0) atomicAdd(&g_cntO[b * 16 + qt], 1);
    } else {
        // ---- out-projection role ----
        const int obid = bid - 1280;       // 0..255
        const int mb   = obid >> 3;        // m-block 0..31  (== b*16 + qt)
        const int nbx  = obid & 7;
        if (tid == 0) { while (ld_acq(&g_cntO[mb]) < 16) { } }
        __syncthreads();
        out_work(sbuf, mb * 128, nbx * 128, bias, out);
    }
}

// ===========================================================================
extern "C" void kernel_launch(void* const* d_in, const int* in_sizes, int n_in,
                              void* d_out, int out_size)
{
    (void)in_sizes; (void)n_in; (void)out_size;
    const float* x  = (const float*)d_in[0];
    const float* Wq = (const float*)d_in[1];
    const float* Wk = (const float*)d_in[2];
    const float* Wv = (const float*)d_in[3];
    const float* Wo = (const float*)d_in[4];
    const float* bo = (const float*)d_in[5];
    float* out = (float*)d_out;

    cudaFuncSetAttribute(mega_kernel,
                         cudaFuncAttributeMaxDynamicSharedMemorySize, MEGA_SMEM);

    const int nTot = NX4 + 4 * NW4;                 // 2,097,152 items
    cvt_all_kernel<<<nTot / 256, 256>>>(x, Wq, Wk, Wv, Wo);
    mega_kernel<<<1536, 256, MEGA_SMEM>>>(bo, out);
}